// round 4
// baseline (speedup 1.0000x reference)
#include <cuda_runtime.h>

// InfluenceProp R4: 2 samples/CTA (512 thr, M=112 rows), FFMA2 math,
// cp.async double-buffered weight pipeline across all 12 weight chunks
// (prefetch depth 2, spans layer boundaries). Folded broadcast biases as R2/R3.

#define K_N 50
#define E_N 128
#define ROWS_PAD 112         // 2 samples: rows 0..49 (s0), 56..105 (s1), pads zeroed
#define ASTR 132             // activation row stride (floats)
#define WSTR 132             // weight row stride (floats)
#define N_CHUNKS 12          // global weight-chunk schedule length

typedef unsigned long long u64;

__device__ __forceinline__ u64 pack2s(float x) {
    u64 r; asm("mov.b64 %0, {%1, %1};" : "=l"(r) : "f"(x)); return r;
}
__device__ __forceinline__ void fma2(u64& d, u64 a, u64 b) {
    asm("fma.rn.f32x2 %0, %1, %2, %0;" : "+l"(d) : "l"(a), "l"(b));
}
__device__ __forceinline__ float2 unpack2(u64 v) {
    float2 f; asm("mov.b64 {%0, %1}, %2;" : "=f"(f.x), "=f"(f.y) : "l"(v)); return f;
}

// async-copy one 64x128 fp32 weight chunk into smem buffer (all 512 threads)
__device__ __forceinline__ void issue_chunk(const float* __restrict__ w,
                                            float* dstBase, int tid) {
#pragma unroll
    for (int t = 0; t < 4; ++t) {
        int idx = tid + t * 512;          // 0..2047 float4 slots
        int row = idx >> 5;
        int c4  = idx & 31;
        unsigned dst = (unsigned)__cvta_generic_to_shared(dstBase + row * WSTR + c4 * 4);
        asm volatile("cp.async.cg.shared.global [%0], [%1], 16;"
                     :: "r"(dst), "l"(w + row * 128 + c4 * 4));
    }
    asm volatile("cp.async.commit_group;" ::: "memory");
}

// GEMM over rows 0..111: out[r][n] = relu(sum_k in[r][k]*W[k][n] + vec_s(r)[n])
// chunks [first, first+n) of the global schedule; chunk c<2 reads in0, else in1.
__device__ __forceinline__ void gemm_layer(
    int firstChunk, int nChunks,
    const float* __restrict__ in0, const float* __restrict__ in1,
    const float* __restrict__ sVec0, const float* __restrict__ sVec1,
    float* __restrict__ sOut,
    float* __restrict__ sW0, float* __restrict__ sW1,
    const float* __restrict__ w_fus, const float* __restrict__ w_c1,
    const float* __restrict__ w_c2,  const float* __restrict__ w_a1,
    const float* __restrict__ w_a2,
    int tid)
{
    const int tx = tid & 31;
    const int ty = tid >> 5;        // 0..15

    u64 acc[7][2];
#pragma unroll
    for (int j = 0; j < 7; ++j) { acc[j][0] = 0ull; acc[j][1] = 0ull; }

    for (int c = 0; c < nChunks; ++c) {
        int i = firstChunk + c;
        // wait for chunk i's cp.async group (keep 1 in flight unless global last)
        if (i < N_CHUNKS - 1)
            asm volatile("cp.async.wait_group 1;" ::: "memory");
        else
            asm volatile("cp.async.wait_group 0;" ::: "memory");
        __syncthreads();

        const float* sWc = (i & 1) ? sW1 : sW0;
        const float* src = (c < 2) ? (in0 + c * 64) : (in1 + (c - 2) * 64);

#pragma unroll 4
        for (int i0 = 0; i0 < 64; i0 += 4) {
            ulonglong2 w0 = *(const ulonglong2*)(sWc + (i0 + 0) * WSTR + tx * 4);
            ulonglong2 w1 = *(const ulonglong2*)(sWc + (i0 + 1) * WSTR + tx * 4);
            ulonglong2 w2 = *(const ulonglong2*)(sWc + (i0 + 2) * WSTR + tx * 4);
            ulonglong2 w3 = *(const ulonglong2*)(sWc + (i0 + 3) * WSTR + tx * 4);
#pragma unroll
            for (int j = 0; j < 7; ++j) {
                float4 a = *(const float4*)(src + (ty + 16 * j) * ASTR + i0);
                u64 p;
                p = pack2s(a.x); fma2(acc[j][0], p, w0.x); fma2(acc[j][1], p, w0.y);
                p = pack2s(a.y); fma2(acc[j][0], p, w1.x); fma2(acc[j][1], p, w1.y);
                p = pack2s(a.z); fma2(acc[j][0], p, w2.x); fma2(acc[j][1], p, w2.y);
                p = pack2s(a.w); fma2(acc[j][0], p, w3.x); fma2(acc[j][1], p, w3.y);
            }
        }
        __syncthreads();   // all reads of sW[i&1] and of inputs (last iter) done

        // prefetch chunk i+2 into the buffer just freed
        int nx = i + 2;
        if (nx < N_CHUNKS) {
            const float* w;
            if      (nx < 4)  w = w_fus + (size_t)nx * 8192;
            else if (nx < 6)  w = w_c1  + (size_t)(nx - 4) * 8192;
            else if (nx < 8)  w = w_c2  + (size_t)(nx - 6) * 8192;
            else if (nx < 10) w = w_a1  + (size_t)(nx - 8) * 8192;
            else              w = w_a2  + (size_t)(nx - 10) * 8192;
            issue_chunk(w, (nx & 1) ? sW1 : sW0, tid);
        }
    }

    // epilogue: bias + relu (in-place safe: trailing barrier above)
#pragma unroll
    for (int j = 0; j < 7; ++j) {
        int r = ty + 16 * j;                  // 0..111
        int rr = (r >= 56) ? r - 56 : r;
        if (rr < K_N) {
            const float* bv = (r < 56) ? sVec0 : sVec1;
            float4 bias = *(const float4*)(bv + tx * 4);
            float2 lo = unpack2(acc[j][0]);
            float2 hi = unpack2(acc[j][1]);
            float4 o;
            o.x = fmaxf(lo.x + bias.x, 0.f);
            o.y = fmaxf(lo.y + bias.y, 0.f);
            o.z = fmaxf(hi.x + bias.z, 0.f);
            o.w = fmaxf(hi.y + bias.w, 0.f);
            *(float4*)(sOut + r * ASTR + tx * 4) = o;
        }
    }
}

// per-sample folded bias: sVec[s][n] = sum_i sX[s][i]*gWbot[i][n] + gB[n]
__device__ __forceinline__ void prep_vec2(
    const float* __restrict__ gWbot, const float* __restrict__ gB,
    const float* __restrict__ sX,    // [2][128]
    float* __restrict__ sVec,        // [2][128]
    float* __restrict__ sTmp,        // [512]
    int tid)
{
    int col = tid & 127;
    int seg = tid >> 7;              // 0..3
    int s   = seg >> 1;
    int half = seg & 1;
    float a = (half == 0) ? gB[col] : 0.f;
    int i0 = half * 64;
#pragma unroll 8
    for (int i = 0; i < 64; ++i)
        a = fmaf(sX[s * 128 + i0 + i], gWbot[(size_t)(i0 + i) * 128 + col], a);
    sTmp[tid] = a;
    __syncthreads();
    if (tid < 256) {
        int ss = tid >> 7, cc = tid & 127;
        sVec[ss * 128 + cc] = sTmp[ss * 256 + cc] + sTmp[ss * 256 + 128 + cc];
    }
}

__global__ __launch_bounds__(512, 1)
void influence_kernel(
    const float* __restrict__ u_embs, const float* __restrict__ i_embs,
    const int*   __restrict__ act_users,
    const float* __restrict__ emb_table, const float* __restrict__ prof_table,
    const float* __restrict__ w_fus, const float* __restrict__ b_fus,
    const float* __restrict__ w_c1,  const float* __restrict__ b_c1,
    const float* __restrict__ w_c2,  const float* __restrict__ b_c2,
    const float* __restrict__ w_a1,  const float* __restrict__ b_a1,
    const float* __restrict__ w_a2,  const float* __restrict__ b_a2,
    const float* __restrict__ w_a3,  const float* __restrict__ b_a3,
    float* __restrict__ out_combined, float* __restrict__ out_att)
{
    extern __shared__ float smem[];
    float* bufA  = smem;                        // [112][132]
    float* bufB  = bufA + ROWS_PAD * ASTR;      // [112][132]
    float* sW0   = bufB + ROWS_PAD * ASTR;      // [64][132]
    float* sW1   = sW0 + 64 * WSTR;             // [64][132]
    float* sVecS = sW1 + 64 * WSTR;             // [128]  shared-bias vector
    float* sVec2 = sVecS + 128;                 // [2][128] per-sample vectors
    float* sX    = sVec2 + 256;                 // [2][128]
    float* sTmp  = sX + 256;                    // [512]
    float* sScore= sTmp + 512;                  // [128]
    float* sAtt  = sScore + 128;                // [128]
    int*   sIdx  = (int*)(sAtt + 128);          // [128]

    const int tid = threadIdx.x;
    const int b0  = blockIdx.x * 2;

    // start weight pipeline immediately (overlaps gather)
    issue_chunk(w_fus,        sW0, tid);
    issue_chunk(w_fus + 8192, sW1, tid);

    // neighbor indices for both samples
    if (tid < 2 * K_N) {
        int s = tid / K_N, k = tid - s * K_N;
        sIdx[s * 64 + k] = act_users[(size_t)(b0 + s) * K_N + k];
    }
    // zero pad rows (50..55, 106..111) of both buffers, cols 0..127
    if (tid < 512) {
        for (int idx = tid; idx < 12 * 128; idx += 512) {
            int r = idx >> 7;
            int row = (r < 6) ? (50 + r) : (100 + r);
            int c = idx & 127;
            bufA[row * ASTR + c] = 0.f;
            bufB[row * ASTR + c] = 0.f;
        }
    }
    if (tid < 128) sVecS[tid] = b_fus[tid];
    __syncthreads();

    // gather: bufA[row]=emb, bufB[row]=prof (row = s*56+k)
    for (int idx = tid; idx < 2 * K_N * 64; idx += 512) {
        int s = idx / (K_N * 64);
        int rem = idx - s * (K_N * 64);
        int k = rem >> 6, q = rem & 63;
        int u = sIdx[s * 64 + k];
        int row = s * 56 + k;
        if (q < 32)
            *(float4*)(bufA + row * ASTR + q * 4) =
                *(const float4*)(emb_table + (size_t)u * 128 + q * 4);
        else
            *(float4*)(bufB + row * ASTR + (q - 32) * 4) =
                *(const float4*)(prof_table + (size_t)u * 128 + (q - 32) * 4);
    }

    // L1 (chunks 0-3): fused = relu([emb|prof]@w_fus + b) -> bufA
    gemm_layer(0, 4, bufA, bufB, sVecS, sVecS, bufA, sW0, sW1,
               w_fus, w_c1, w_c2, w_a1, w_a2, tid);
    __syncthreads();

    // prep per-sample vec: i_emb @ w_c1_bot + b_c1
    if (tid < 64) {
        int s = tid >> 5, q = tid & 31;
        *(float4*)(sX + s * 128 + q * 4) =
            *(const float4*)(i_embs + (size_t)(b0 + s) * 128 + q * 4);
    }
    __syncthreads();
    prep_vec2(w_c1 + (size_t)128 * 128, b_c1, sX, sVec2, sTmp, tid);

    // L2 (chunks 4-5): c1 = relu(fused@w_c1_top + vec) -> bufB
    gemm_layer(4, 2, bufA, nullptr, sVec2, sVec2 + 128, bufB, sW0, sW1,
               w_fus, w_c1, w_c2, w_a1, w_a2, tid);
    __syncthreads();

    if (tid < 128) sVecS[tid] = b_c2[tid];
    // L3 (chunks 6-7): coup = relu(c1@w_c2 + b) -> bufA (kept)
    gemm_layer(6, 2, bufB, nullptr, sVecS, sVecS, bufA, sW0, sW1,
               w_fus, w_c1, w_c2, w_a1, w_a2, tid);
    __syncthreads();

    if (tid < 64) {
        int s = tid >> 5, q = tid & 31;
        *(float4*)(sX + s * 128 + q * 4) =
            *(const float4*)(u_embs + (size_t)(b0 + s) * 128 + q * 4);
    }
    __syncthreads();
    prep_vec2(w_a1 + (size_t)128 * 128, b_a1, sX, sVec2, sTmp, tid);

    // L4 (chunks 8-9): h = relu(coup@w_a1_top + vec) -> bufB
    gemm_layer(8, 2, bufA, nullptr, sVec2, sVec2 + 128, bufB, sW0, sW1,
               w_fus, w_c1, w_c2, w_a1, w_a2, tid);
    __syncthreads();

    if (tid < 128) sVecS[tid] = b_a2[tid];
    // L5 (chunks 10-11): h2 = relu(h@w_a2 + b) -> bufB (in-place safe)
    gemm_layer(10, 2, bufB, nullptr, sVecS, sVecS, bufB, sW0, sW1,
               w_fus, w_c1, w_c2, w_a1, w_a2, tid);
    __syncthreads();

    // scores: warp w handles sample s=w>>3, k = (w&7), +8...
    {
        int warp = tid >> 5, lane = tid & 31;
        int s = warp >> 3, w8 = warp & 7;
        for (int k = w8; k < K_N; k += 8) {
            int row = s * 56 + k;
            float p = 0.f;
#pragma unroll
            for (int t = 0; t < 4; ++t) {
                int i = lane + 32 * t;
                p = fmaf(bufB[row * ASTR + i], w_a3[i], p);
            }
#pragma unroll
            for (int o = 16; o; o >>= 1)
                p += __shfl_xor_sync(0xffffffffu, p, o);
            if (lane == 0) sScore[s * 64 + k] = p + b_a3[0];
        }
    }
    __syncthreads();

    // softmax per sample: warp 0 -> s0, warp 8 -> s1
    {
        int warp = tid >> 5;
        if (warp == 0 || warp == 8) {
            int s = warp >> 3, lane = tid & 31;
            float v1 = (lane < K_N)      ? sScore[s * 64 + lane]      : -1e30f;
            float v2 = (lane + 32 < K_N) ? sScore[s * 64 + lane + 32] : -1e30f;
            float m = fmaxf(v1, v2);
#pragma unroll
            for (int o = 16; o; o >>= 1)
                m = fmaxf(m, __shfl_xor_sync(0xffffffffu, m, o));
            float e1 = (lane < K_N)      ? expf(v1 - m) : 0.f;
            float e2 = (lane + 32 < K_N) ? expf(v2 - m) : 0.f;
            float sum = e1 + e2;
#pragma unroll
            for (int o = 16; o; o >>= 1)
                sum += __shfl_xor_sync(0xffffffffu, sum, o);
            float inv = 1.f / sum;
            if (lane < K_N)      sAtt[s * 64 + lane]      = e1 * inv;
            if (lane + 32 < K_N) sAtt[s * 64 + lane + 32] = e2 * inv;
        }
    }
    __syncthreads();

    // combined[e] = sum_k att[k]*coup[k][e]  (coup in bufA)
    if (tid < 256) {
        int s = tid >> 7, col = tid & 127;
        float acc = 0.f;
#pragma unroll
        for (int k = 0; k < K_N; ++k)
            acc = fmaf(sAtt[s * 64 + k], bufA[(s * 56 + k) * ASTR + col], acc);
        out_combined[(size_t)(b0 + s) * 128 + col] = acc;
    } else {
        int t = tid - 256;
        int s = t >> 6, k = t & 63;
        if (s < 2 && k < K_N)
            out_att[(size_t)(b0 + s) * K_N + k] = sAtt[s * 64 + k];
    }
}

extern "C" void kernel_launch(void* const* d_in, const int* in_sizes, int n_in,
                              void* d_out, int out_size) {
    const float* u_embs = (const float*)d_in[1];
    const float* i_embs = (const float*)d_in[3];
    const int*   act    = (const int*)d_in[4];
    const float* table  = (const float*)d_in[5];
    const float* prof   = (const float*)d_in[6];
    const float* w_fus  = (const float*)d_in[7];
    const float* b_fus  = (const float*)d_in[8];
    const float* w_c1   = (const float*)d_in[9];
    const float* b_c1   = (const float*)d_in[10];
    const float* w_c2   = (const float*)d_in[11];
    const float* b_c2   = (const float*)d_in[12];
    const float* w_a1   = (const float*)d_in[13];
    const float* b_a1   = (const float*)d_in[14];
    const float* w_a2   = (const float*)d_in[15];
    const float* b_a2   = (const float*)d_in[16];
    const float* w_a3   = (const float*)d_in[17];
    const float* b_a3   = (const float*)d_in[18];

    int B = in_sizes[0];   // 4096

    float* out_combined = (float*)d_out;
    float* out_att      = out_combined + (size_t)B * E_N;

    size_t smem_floats = (size_t)(2 * ROWS_PAD * ASTR)   // bufA, bufB
                       + 2 * 64 * WSTR                    // sW0, sW1
                       + 128 + 256 + 256 + 512            // sVecS, sVec2, sX, sTmp
                       + 128 + 128 + 128;                 // sScore, sAtt, sIdx
    size_t smem_bytes = smem_floats * sizeof(float);
    cudaFuncSetAttribute(influence_kernel,
                         cudaFuncAttributeMaxDynamicSharedMemorySize,
                         (int)smem_bytes);

    influence_kernel<<<B / 2, 512, smem_bytes>>>(
        u_embs, i_embs, act, table, prof,
        w_fus, b_fus, w_c1, b_c1, w_c2, b_c2,
        w_a1, b_a1, w_a2, b_a2, w_a3, b_a3,
        out_combined, out_att);
}

// round 6
// speedup vs baseline: 1.5324x; 1.5324x over previous
#include <cuda_runtime.h>
#include <cuda_bf16.h>
#include <cstdint>

// InfluenceProp R6: mma.sync (HMMA) bf16x3-split pipeline for base sm_103.
// (tcgen05 is sm_103a-only and the harness targets plain sm_103.)
// 1 CTA = 2 samples, M=128 rows, 256 threads / 8 warps (warp w owns m-strip
// [16w,16w+16)). Weights pre-split hi/lo bf16, transposed to [n][k], stored in
// the exact XOR-swizzled smem image; cp.async double-buffered. Activations are
// re-split to bf16 hi/lo in each layer epilogue. fp32 accumulate in HMMA.

#define K_N 50

// ---------------- gmem scratch ----------------
__device__ __align__(1024) __nv_bfloat16 g_wb[6 * 32768]; // 6 units x {hi 16384, lo 16384} elems
__device__ float g_vec[2ull * 4096 * 128];                // folded biases [which][b][128]
__device__ float g_coup[2048ull * 128 * 128];             // per-CTA coup fp32

// ---------------- smem byte offsets ----------------
#define SM_AHI   0
#define SM_ALO   32768
#define SM_B0H   65536
#define SM_B0L   98304
#define SM_B1H   131072
#define SM_B1L   163840
#define SM_IDX   196608
#define SM_BFUS  197120
#define SM_BC2   197632
#define SM_BA2   198144
#define SM_W3    198656
#define SM_VC1   199168
#define SM_VA1   200192
#define SM_SCORE 201216
#define SM_ATT   201728
#define SM_TOTAL 202240

// tile layout: row r (0-127), 256 B/row; 16B chunk c stored at (c ^ (r&7))
__device__ __host__ __forceinline__ int tile_off(int r, int c) {
    return r * 256 + ((c ^ (r & 7)) << 4);
}

__device__ __forceinline__ uint32_t smem_u32(const void* p) {
    uint32_t a;
    asm("{ .reg .u64 t; cvta.to.shared.u64 t, %1; cvt.u32.u64 %0, t; }" : "=r"(a) : "l"(p));
    return a;
}

#define LDSM4(r0, r1, r2, r3, addr) \
    asm volatile("ldmatrix.sync.aligned.m8n8.x4.shared.b16 {%0,%1,%2,%3}, [%4];" \
                 : "=r"(r0), "=r"(r1), "=r"(r2), "=r"(r3) : "r"(addr))
#define LDSM2(r0, r1, addr) \
    asm volatile("ldmatrix.sync.aligned.m8n8.x2.shared.b16 {%0,%1}, [%2];" \
                 : "=r"(r0), "=r"(r1) : "r"(addr))
#define MMA(ac, a0, a1, a2, a3, b0, b1) \
    asm volatile("mma.sync.aligned.m16n8k16.row.col.f32.bf16.bf16.f32 " \
                 "{%0,%1,%2,%3},{%4,%5,%6,%7},{%8,%9},{%0,%1,%2,%3};" \
                 : "+f"((ac)[0]), "+f"((ac)[1]), "+f"((ac)[2]), "+f"((ac)[3]) \
                 : "r"(a0), "r"(a1), "r"(a2), "r"(a3), "r"(b0), "r"(b1))

__device__ __forceinline__ uint32_t pk2(__nv_bfloat16 lo, __nv_bfloat16 hi) {
    return (uint32_t)__bfloat16_as_ushort(hi) << 16 | __bfloat16_as_ushort(lo);
}
__device__ __forceinline__ void split1(float x, __nv_bfloat16& h, __nv_bfloat16& l) {
    h = __float2bfloat16_rn(x);
    l = __float2bfloat16_rn(x - __bfloat162float(h));
}

// ---------------- prepass 1: weight split + transpose + swizzle ----------------
__global__ void prep_weights(
    const float* __restrict__ w_fus, const float* __restrict__ w_c1,
    const float* __restrict__ w_c2,  const float* __restrict__ w_a1,
    const float* __restrict__ w_a2)
{
    int u = blockIdx.x;
    const float* base; int koff = 0;
    if      (u == 0) { base = w_fus; }
    else if (u == 1) { base = w_fus; koff = 128; }
    else if (u == 2) { base = w_c1; }
    else if (u == 3) { base = w_c2; }
    else if (u == 4) { base = w_a1; }
    else             { base = w_a2; }

    for (int e = threadIdx.x; e < 16384; e += blockDim.x) {
        int n = e >> 7, k = e & 127;
        float v = base[(size_t)(k + koff) * 128 + n];
        __nv_bfloat16 hi, lo;
        split1(v, hi, lo);
        int elem = (n * 256 + (((k >> 3) ^ (n & 7)) << 4) + (k & 7) * 2) >> 1;
        g_wb[(size_t)u * 32768 + elem]         = hi;
        g_wb[(size_t)u * 32768 + 16384 + elem] = lo;
    }
}

// ---------------- prepass 2: folded per-sample bias vectors ----------------
__global__ void prep_vecs(
    const float* __restrict__ i_embs, const float* __restrict__ u_embs,
    const float* __restrict__ w_c1,   const float* __restrict__ b_c1,
    const float* __restrict__ w_a1,   const float* __restrict__ b_a1,
    int Btot)
{
    int b = blockIdx.x;
    int which = blockIdx.y;
    int col = threadIdx.x;
    const float* emb = which ? u_embs : i_embs;
    const float* W   = (which ? w_a1 : w_c1) + (size_t)128 * 128;
    const float* bb  = which ? b_a1 : b_c1;
    float acc = bb[col];
#pragma unroll 4
    for (int i = 0; i < 128; ++i)
        acc = fmaf(emb[(size_t)b * 128 + i], W[(size_t)i * 128 + col], acc);
    g_vec[(size_t)which * Btot * 128 + (size_t)b * 128 + col] = acc;
}

// ---------------- main kernel pieces ----------------
__device__ __forceinline__ void copy_unit(int u, uint32_t dstAddr, int tid) {
    const char* src = (const char*)g_wb + (size_t)u * 65536;
#pragma unroll
    for (int t = 0; t < 16; ++t) {
        int i = tid + t * 256;             // 0..4095 16B lines
        asm volatile("cp.async.cg.shared.global [%0], [%1], 16;"
                     :: "r"(dstAddr + i * 16), "l"(src + (size_t)i * 16));
    }
    asm volatile("cp.async.commit_group;" ::: "memory");
}

__device__ __forceinline__ void sweep(
    float (&acc)[16][4],
    uint32_t aHi, uint32_t aLo, uint32_t bHi, uint32_t bLo,
    int w, int l)
{
    const int rA = 16 * w + (l & 15);
    const uint32_t aRow = (uint32_t)rA * 256;
    const int axor = rA & 7;
    const int khA = l >> 4;
    const int bxor = l & 7;
    const uint32_t bRow = (uint32_t)(l & 7) * 256;
    const int khB = (l >> 3) & 1;

#pragma unroll 1
    for (int ks = 0; ks < 8; ++ks) {
        uint32_t aoff = aRow + (uint32_t)((((2 * ks + khA)) ^ axor) << 4);
        uint32_t ah0, ah1, ah2, ah3, al0, al1, al2, al3;
        LDSM4(ah0, ah1, ah2, ah3, aHi + aoff);
        LDSM4(al0, al1, al2, al3, aLo + aoff);
        uint32_t bko = bRow + (uint32_t)((((2 * ks + khB)) ^ bxor) << 4);
#pragma unroll
        for (int t = 0; t < 16; ++t) {
            uint32_t bo = (uint32_t)t * 2048 + bko;
            uint32_t bh0, bh1, bl0, bl1;
            LDSM2(bh0, bh1, bHi + bo);
            LDSM2(bl0, bl1, bLo + bo);
            MMA(acc[t], ah0, ah1, ah2, ah3, bh0, bh1);
            MMA(acc[t], al0, al1, al2, al3, bh0, bh1);
            MMA(acc[t], ah0, ah1, ah2, ah3, bl0, bl1);
        }
    }
}

// gather table rows -> split -> swizzled A tiles (rows s*64+k)
__device__ __forceinline__ void gatherA(
    const float* __restrict__ tbl, const int* sIdx, char* smemc, int tid)
{
    for (int idx = tid; idx < 1600; idx += 256) {
        int rowi = idx >> 4;                  // 0..99
        int s = (rowi >= 50) ? 1 : 0;
        int k = rowi - s * 50;
        int r = s * 64 + k;
        int c = idx & 15;
        int u = sIdx[s * 64 + k];
        const float4* src = (const float4*)(tbl + (size_t)u * 128 + c * 8);
        float4 v0 = src[0], v1 = src[1];
        __nv_bfloat16 h[8], lo[8];
        split1(v0.x, h[0], lo[0]); split1(v0.y, h[1], lo[1]);
        split1(v0.z, h[2], lo[2]); split1(v0.w, h[3], lo[3]);
        split1(v1.x, h[4], lo[4]); split1(v1.y, h[5], lo[5]);
        split1(v1.z, h[6], lo[6]); split1(v1.w, h[7], lo[7]);
        uint4 hv = make_uint4(pk2(h[0], h[1]), pk2(h[2], h[3]),
                              pk2(h[4], h[5]), pk2(h[6], h[7]));
        uint4 lv = make_uint4(pk2(lo[0], lo[1]), pk2(lo[2], lo[3]),
                              pk2(lo[4], lo[5]), pk2(lo[6], lo[7]));
        int off = tile_off(r, c);
        *(uint4*)(smemc + SM_AHI + off) = hv;
        *(uint4*)(smemc + SM_ALO + off) = lv;
    }
}

// bias + relu -> re-split to A tiles (opt: fp32 coup to gmem); resets acc
__device__ __forceinline__ void epilogueA(
    float (&acc)[16][4], char* smemc,
    const float* bias0, const float* bias1,
    float* coupBase, int w, int l)
{
    int q = 16 * w + (l >> 2);
    int p2 = (l & 3) * 2;
    const float* bA = (q < 64) ? bias0 : bias1;
    int r0 = q, r1 = q + 8;
#pragma unroll
    for (int t = 0; t < 16; ++t) {
        int n = 8 * t + p2;
        float y00 = fmaxf(acc[t][0] + bA[n],     0.f);
        float y01 = fmaxf(acc[t][1] + bA[n + 1], 0.f);
        float y10 = fmaxf(acc[t][2] + bA[n],     0.f);
        float y11 = fmaxf(acc[t][3] + bA[n + 1], 0.f);
        acc[t][0] = 0.f; acc[t][1] = 0.f; acc[t][2] = 0.f; acc[t][3] = 0.f;
        __nv_bfloat16 h0, l0, h1, l1;
        split1(y00, h0, l0); split1(y01, h1, l1);
        int o0 = tile_off(r0, t) + p2 * 2;
        *(uint32_t*)(smemc + SM_AHI + o0) = pk2(h0, h1);
        *(uint32_t*)(smemc + SM_ALO + o0) = pk2(l0, l1);
        split1(y10, h0, l0); split1(y11, h1, l1);
        int o1 = tile_off(r1, t) + p2 * 2;
        *(uint32_t*)(smemc + SM_AHI + o1) = pk2(h0, h1);
        *(uint32_t*)(smemc + SM_ALO + o1) = pk2(l0, l1);
        if (coupBase) {
            *(float2*)(coupBase + (size_t)r0 * 128 + n) = make_float2(y00, y01);
            *(float2*)(coupBase + (size_t)r1 * 128 + n) = make_float2(y10, y11);
        }
    }
}

// last layer: bias+relu, dot with w3, reduce quad -> sScore
__device__ __forceinline__ void epilogueScore(
    float (&acc)[16][4], const float* ba2, const float* w3, float b3,
    float* sScore, int w, int l)
{
    int q = 16 * w + (l >> 2);
    int p2 = (l & 3) * 2;
    float p0 = 0.f, p1 = 0.f;
#pragma unroll
    for (int t = 0; t < 16; ++t) {
        int n = 8 * t + p2;
        p0 = fmaf(fmaxf(acc[t][0] + ba2[n],     0.f), w3[n],     p0);
        p0 = fmaf(fmaxf(acc[t][1] + ba2[n + 1], 0.f), w3[n + 1], p0);
        p1 = fmaf(fmaxf(acc[t][2] + ba2[n],     0.f), w3[n],     p1);
        p1 = fmaf(fmaxf(acc[t][3] + ba2[n + 1], 0.f), w3[n + 1], p1);
    }
    p0 += __shfl_xor_sync(0xffffffffu, p0, 1);
    p0 += __shfl_xor_sync(0xffffffffu, p0, 2);
    p1 += __shfl_xor_sync(0xffffffffu, p1, 1);
    p1 += __shfl_xor_sync(0xffffffffu, p1, 2);
    if ((l & 3) == 0) {
        sScore[q]     = p0 + b3;
        sScore[q + 8] = p1 + b3;
    }
}

#define WAITG(n) asm volatile("cp.async.wait_group %0;" :: "n"(n) : "memory")

__global__ __launch_bounds__(256, 1)
void influence_main(
    const float* __restrict__ act_users_f,  // actually int*, cast below
    const float* __restrict__ emb_table, const float* __restrict__ prof_table,
    const float* __restrict__ b_fus, const float* __restrict__ b_c2,
    const float* __restrict__ b_a2,  const float* __restrict__ w_a3,
    const float* __restrict__ b_a3,
    int Btot,
    float* __restrict__ out_combined, float* __restrict__ out_att)
{
    extern __shared__ char smemc[];
    const int tid = threadIdx.x;
    const int w = tid >> 5, l = tid & 31;
    const int b0 = blockIdx.x * 2;
    const int* act_users = (const int*)act_users_f;
    uint32_t sb = smem_u32(smemc);

    int* sIdx     = (int*)(smemc + SM_IDX);
    float* sBfus  = (float*)(smemc + SM_BFUS);
    float* sBc2   = (float*)(smemc + SM_BC2);
    float* sBa2   = (float*)(smemc + SM_BA2);
    float* sW3    = (float*)(smemc + SM_W3);
    float* sVC1   = (float*)(smemc + SM_VC1);
    float* sVA1   = (float*)(smemc + SM_VA1);
    float* sScore = (float*)(smemc + SM_SCORE);
    float* sAtt   = (float*)(smemc + SM_ATT);
    float* coup   = g_coup + (size_t)blockIdx.x * 16384;

    // start weight pipeline: unit0 -> B0, unit1 -> B1
    copy_unit(0, sb + SM_B0H, tid);
    copy_unit(1, sb + SM_B1H, tid);

    if (tid < 100) {
        int s = tid / 50, k = tid - s * 50;
        sIdx[s * 64 + k] = act_users[(size_t)(b0 + s) * K_N + k];
    }
    if (tid < 128) {
        sBfus[tid] = b_fus[tid];
        sBc2[tid]  = b_c2[tid];
        sBa2[tid]  = b_a2[tid];
        sW3[tid]   = w_a3[tid];
    }
    if (tid >= 128 && tid < 256) {
        int c = tid - 128;
        sVC1[c]       = g_vec[(size_t)(b0 + 0) * 128 + c];
        sVC1[128 + c] = g_vec[(size_t)(b0 + 1) * 128 + c];
        sVA1[c]       = g_vec[(size_t)Btot * 128 + (size_t)(b0 + 0) * 128 + c];
        sVA1[128 + c] = g_vec[(size_t)Btot * 128 + (size_t)(b0 + 1) * 128 + c];
    }
    // zero pad rows (50-63, 114-127)
    for (int idx = tid; idx < 28 * 16; idx += 256) {
        int pr = idx >> 4;
        int r = (pr < 14) ? (50 + pr) : (100 + pr);
        int c = idx & 15;
        int off = tile_off(r, c);
        *(uint4*)(smemc + SM_AHI + off) = make_uint4(0, 0, 0, 0);
        *(uint4*)(smemc + SM_ALO + off) = make_uint4(0, 0, 0, 0);
    }
    __syncthreads();                       // sIdx visible
    gatherA(emb_table, sIdx, smemc, tid);

    float acc[16][4];
#pragma unroll
    for (int t = 0; t < 16; ++t) {
        acc[t][0] = 0.f; acc[t][1] = 0.f; acc[t][2] = 0.f; acc[t][3] = 0.f;
    }

    WAITG(1); __syncthreads();             // A(emb) + unit0 ready
    sweep(acc, sb + SM_AHI, sb + SM_ALO, sb + SM_B0H, sb + SM_B0L, w, l);
    __syncthreads();                       // B0 free
    copy_unit(2, sb + SM_B0H, tid);
    gatherA(prof_table, sIdx, smemc, tid); // rewrite A (pads stay zero)
    WAITG(1); __syncthreads();             // A(prof) + unit1 ready
    sweep(acc, sb + SM_AHI, sb + SM_ALO, sb + SM_B1H, sb + SM_B1L, w, l);
    __syncthreads();                       // B1 free
    copy_unit(3, sb + SM_B1H, tid);
    epilogueA(acc, smemc, sBfus, sBfus, nullptr, w, l);     // L1 -> fused
    WAITG(1); __syncthreads();
    sweep(acc, sb + SM_AHI, sb + SM_ALO, sb + SM_B0H, sb + SM_B0L, w, l);   // L2
    __syncthreads();
    copy_unit(4, sb + SM_B0H, tid);
    epilogueA(acc, smemc, sVC1, sVC1 + 128, nullptr, w, l); // L2 -> c1
    WAITG(1); __syncthreads();
    sweep(acc, sb + SM_AHI, sb + SM_ALO, sb + SM_B1H, sb + SM_B1L, w, l);   // L3
    __syncthreads();
    copy_unit(5, sb + SM_B1H, tid);
    epilogueA(acc, smemc, sBc2, sBc2, coup, w, l);          // L3 -> coup (+gmem)
    WAITG(1); __syncthreads();
    sweep(acc, sb + SM_AHI, sb + SM_ALO, sb + SM_B0H, sb + SM_B0L, w, l);   // L4
    __syncthreads();
    epilogueA(acc, smemc, sVA1, sVA1 + 128, nullptr, w, l); // L4 -> h
    WAITG(0); __syncthreads();
    sweep(acc, sb + SM_AHI, sb + SM_ALO, sb + SM_B1H, sb + SM_B1L, w, l);   // L5
    epilogueScore(acc, sBa2, sW3, b_a3[0], sScore, w, l);
    __syncthreads();

    // softmax per sample (warp 0 -> s0, warp 1 -> s1)
    if (w < 2) {
        int base = w * 64;
        float v1 = (l < K_N)      ? sScore[base + l]      : -1e30f;
        float v2 = (l + 32 < K_N) ? sScore[base + l + 32] : -1e30f;
        float m = fmaxf(v1, v2);
#pragma unroll
        for (int o = 16; o; o >>= 1)
            m = fmaxf(m, __shfl_xor_sync(0xffffffffu, m, o));
        float e1 = (l < K_N)      ? expf(v1 - m) : 0.f;
        float e2 = (l + 32 < K_N) ? expf(v2 - m) : 0.f;
        float sum = e1 + e2;
#pragma unroll
        for (int o = 16; o; o >>= 1)
            sum += __shfl_xor_sync(0xffffffffu, sum, o);
        float inv = 1.f / sum;
        if (l < K_N)      sAtt[base + l]      = e1 * inv;
        if (l + 32 < K_N) sAtt[base + l + 32] = e2 * inv;
    }
    __syncthreads();

    // combined[s][col] = sum_k att[s][k] * coup[s*64+k][col]
    {
        int s = tid >> 7, col = tid & 127;
        float a = 0.f;
#pragma unroll 2
        for (int k = 0; k < K_N; ++k)
            a = fmaf(sAtt[s * 64 + k], coup[(size_t)(s * 64 + k) * 128 + col], a);
        out_combined[(size_t)(b0 + s) * 128 + col] = a;
    }
    if (tid < 2 * K_N) {
        int s = tid / K_N, k = tid - s * K_N;
        out_att[(size_t)(b0 + s) * K_N + k] = sAtt[s * 64 + k];
    }
}

// ---------------- host launcher ----------------
extern "C" void kernel_launch(void* const* d_in, const int* in_sizes, int n_in,
                              void* d_out, int out_size) {
    const float* u_embs = (const float*)d_in[1];
    const float* i_embs = (const float*)d_in[3];
    const float* act    = (const float*)d_in[4];   // int32 data
    const float* table  = (const float*)d_in[5];
    const float* prof   = (const float*)d_in[6];
    const float* w_fus  = (const float*)d_in[7];
    const float* b_fus  = (const float*)d_in[8];
    const float* w_c1   = (const float*)d_in[9];
    const float* b_c1   = (const float*)d_in[10];
    const float* w_c2   = (const float*)d_in[11];
    const float* b_c2   = (const float*)d_in[12];
    const float* w_a1   = (const float*)d_in[13];
    const float* b_a1   = (const float*)d_in[14];
    const float* w_a2   = (const float*)d_in[15];
    const float* b_a2   = (const float*)d_in[16];
    const float* w_a3   = (const float*)d_in[17];
    const float* b_a3   = (const float*)d_in[18];

    int B = in_sizes[0];   // 4096

    float* out_combined = (float*)d_out;
    float* out_att      = out_combined + (size_t)B * 128;

    prep_weights<<<6, 256>>>(w_fus, w_c1, w_c2, w_a1, w_a2);
    prep_vecs<<<dim3(B, 2), 128>>>(i_embs, u_embs, w_c1, b_c1, w_a1, b_a1, B);

    cudaFuncSetAttribute(influence_main,
                         cudaFuncAttributeMaxDynamicSharedMemorySize, SM_TOTAL);
    influence_main<<<B / 2, 256, SM_TOTAL>>>(
        act, table, prof,
        b_fus, b_c2, b_a2, w_a3, b_a3, B,
        out_combined, out_att);
}

// round 7
// speedup vs baseline: 1.6059x; 1.0479x over previous
#include <cuda_runtime.h>
#include <cuda_bf16.h>
#include <cstdint>

// InfluenceProp R7: R6 (HMMA bf16x3-split) with a restructured sweep:
//  - term-major passes (AhiBhi all-t, AloBhi all-t, AhiBlo all-t) so the
//    accumulator RAW chain distance is 16 MMAs instead of 1
//  - B fragments loaded once per k-step via ldmatrix.x4 tile-pairs and held
//    in registers across passes (18 LDSM/ks vs 34)
//  - prep_weights widened to 48 blocks

#define K_N 50

// ---------------- gmem scratch ----------------
__device__ __align__(1024) __nv_bfloat16 g_wb[6 * 32768]; // 6 units x {hi,lo} 16384 elems
__device__ float g_vec[2ull * 4096 * 128];                // folded biases [which][b][128]
__device__ float g_coup[2048ull * 128 * 128];             // per-CTA coup fp32

// ---------------- smem byte offsets ----------------
#define SM_AHI   0
#define SM_ALO   32768
#define SM_B0H   65536
#define SM_B0L   98304
#define SM_B1H   131072
#define SM_B1L   163840
#define SM_IDX   196608
#define SM_BFUS  197120
#define SM_BC2   197632
#define SM_BA2   198144
#define SM_W3    198656
#define SM_VC1   199168
#define SM_VA1   200192
#define SM_SCORE 201216
#define SM_ATT   201728
#define SM_TOTAL 202240

// tile layout: row r (0-127), 256 B/row; 16B chunk c stored at (c ^ (r&7))
__device__ __host__ __forceinline__ int tile_off(int r, int c) {
    return r * 256 + ((c ^ (r & 7)) << 4);
}

__device__ __forceinline__ uint32_t smem_u32(const void* p) {
    uint32_t a;
    asm("{ .reg .u64 t; cvta.to.shared.u64 t, %1; cvt.u32.u64 %0, t; }" : "=r"(a) : "l"(p));
    return a;
}

#define LDSM4(r0, r1, r2, r3, addr) \
    asm volatile("ldmatrix.sync.aligned.m8n8.x4.shared.b16 {%0,%1,%2,%3}, [%4];" \
                 : "=r"(r0), "=r"(r1), "=r"(r2), "=r"(r3) : "r"(addr))
#define MMA(ac, a0, a1, a2, a3, b0, b1) \
    asm volatile("mma.sync.aligned.m16n8k16.row.col.f32.bf16.bf16.f32 " \
                 "{%0,%1,%2,%3},{%4,%5,%6,%7},{%8,%9},{%0,%1,%2,%3};" \
                 : "+f"((ac)[0]), "+f"((ac)[1]), "+f"((ac)[2]), "+f"((ac)[3]) \
                 : "r"(a0), "r"(a1), "r"(a2), "r"(a3), "r"(b0), "r"(b1))

__device__ __forceinline__ uint32_t pk2(__nv_bfloat16 lo, __nv_bfloat16 hi) {
    return (uint32_t)__bfloat16_as_ushort(hi) << 16 | __bfloat16_as_ushort(lo);
}
__device__ __forceinline__ void split1(float x, __nv_bfloat16& h, __nv_bfloat16& l) {
    h = __float2bfloat16_rn(x);
    l = __float2bfloat16_rn(x - __bfloat162float(h));
}

// ---------------- prepass 1: weight split + transpose + swizzle ----------------
__global__ void prep_weights(
    const float* __restrict__ w_fus, const float* __restrict__ w_c1,
    const float* __restrict__ w_c2,  const float* __restrict__ w_a1,
    const float* __restrict__ w_a2)
{
    int u = blockIdx.x >> 3;            // 6 units x 8 parts
    int part = blockIdx.x & 7;
    const float* base; int koff = 0;
    if      (u == 0) { base = w_fus; }
    else if (u == 1) { base = w_fus; koff = 128; }
    else if (u == 2) { base = w_c1; }
    else if (u == 3) { base = w_c2; }
    else if (u == 4) { base = w_a1; }
    else             { base = w_a2; }

    int e0 = part * 2048;
    for (int i = threadIdx.x; i < 2048; i += blockDim.x) {
        int e = e0 + i;
        int n = e >> 7, k = e & 127;
        float v = base[(size_t)(k + koff) * 128 + n];
        __nv_bfloat16 hi, lo;
        split1(v, hi, lo);
        int elem = (n * 256 + (((k >> 3) ^ (n & 7)) << 4) + (k & 7) * 2) >> 1;
        g_wb[(size_t)u * 32768 + elem]         = hi;
        g_wb[(size_t)u * 32768 + 16384 + elem] = lo;
    }
}

// ---------------- prepass 2: folded per-sample bias vectors ----------------
__global__ void prep_vecs(
    const float* __restrict__ i_embs, const float* __restrict__ u_embs,
    const float* __restrict__ w_c1,   const float* __restrict__ b_c1,
    const float* __restrict__ w_a1,   const float* __restrict__ b_a1,
    int Btot)
{
    int b = blockIdx.x;
    int which = blockIdx.y;
    int col = threadIdx.x;
    const float* emb = which ? u_embs : i_embs;
    const float* W   = (which ? w_a1 : w_c1) + (size_t)128 * 128;
    const float* bb  = which ? b_a1 : b_c1;
    float acc = bb[col];
#pragma unroll 4
    for (int i = 0; i < 128; ++i)
        acc = fmaf(emb[(size_t)b * 128 + i], W[(size_t)i * 128 + col], acc);
    g_vec[(size_t)which * Btot * 128 + (size_t)b * 128 + col] = acc;
}

// ---------------- main kernel pieces ----------------
__device__ __forceinline__ void copy_unit(int u, uint32_t dstAddr, int tid) {
    const char* src = (const char*)g_wb + (size_t)u * 65536;
#pragma unroll
    for (int t = 0; t < 16; ++t) {
        int i = tid + t * 256;             // 0..4095 16B lines
        asm volatile("cp.async.cg.shared.global [%0], [%1], 16;"
                     :: "r"(dstAddr + i * 16), "l"(src + (size_t)i * 16));
    }
    asm volatile("cp.async.commit_group;" ::: "memory");
}

// term-major sweep: acc += Ahi*Bhi + Alo*Bhi + Ahi*Blo  over K=128
__device__ __forceinline__ void sweep(
    float (&acc)[16][4],
    uint32_t aHi, uint32_t aLo, uint32_t bHi, uint32_t bLo,
    int w, int l)
{
    const int rA = 16 * w + (l & 15);
    const uint32_t aRowOff = (uint32_t)rA * 256;
    const int axor = rA & 7;
    const int khA = l >> 4;
    // B x4 addressing: lane l -> tile-pair member (l>>4)&1, row l&7, khalf (l>>3)&1
    const uint32_t bLane = (uint32_t)(((l >> 4) & 1) * 2048 + (l & 7) * 256);
    const int bKh  = (l >> 3) & 1;
    const int bxor = l & 7;

#pragma unroll 1
    for (int ks = 0; ks < 8; ++ks) {
        uint32_t aoff = aRowOff + (uint32_t)(((2 * ks + khA) ^ axor) << 4);
        uint32_t ah0, ah1, ah2, ah3, al0, al1, al2, al3;
        LDSM4(ah0, ah1, ah2, ah3, aHi + aoff);
        LDSM4(al0, al1, al2, al3, aLo + aoff);

        uint32_t bko = bLane + (uint32_t)(((2 * ks + bKh) ^ bxor) << 4);

        // load all 16 B-hi fragments (8 tile-pair LDSM4)
        uint32_t bh[16][2];
#pragma unroll
        for (int p = 0; p < 8; ++p)
            LDSM4(bh[2 * p][0], bh[2 * p][1], bh[2 * p + 1][0], bh[2 * p + 1][1],
                  bHi + (uint32_t)p * 4096 + bko);

        // pass 1: Ahi x Bhi  (16 independent MMAs)
#pragma unroll
        for (int t = 0; t < 16; ++t)
            MMA(acc[t], ah0, ah1, ah2, ah3, bh[t][0], bh[t][1]);
        // pass 2: Alo x Bhi  (reuse held B-hi fragments)
#pragma unroll
        for (int t = 0; t < 16; ++t)
            MMA(acc[t], al0, al1, al2, al3, bh[t][0], bh[t][1]);

        // load all 16 B-lo fragments
        uint32_t bl[16][2];
#pragma unroll
        for (int p = 0; p < 8; ++p)
            LDSM4(bl[2 * p][0], bl[2 * p][1], bl[2 * p + 1][0], bl[2 * p + 1][1],
                  bLo + (uint32_t)p * 4096 + bko);

        // pass 3: Ahi x Blo
#pragma unroll
        for (int t = 0; t < 16; ++t)
            MMA(acc[t], ah0, ah1, ah2, ah3, bl[t][0], bl[t][1]);
    }
}

// gather table rows -> split -> swizzled A tiles (rows s*64+k)
__device__ __forceinline__ void gatherA(
    const float* __restrict__ tbl, const int* sIdx, char* smemc, int tid)
{
    for (int idx = tid; idx < 1600; idx += 256) {
        int rowi = idx >> 4;                  // 0..99
        int s = (rowi >= 50) ? 1 : 0;
        int k = rowi - s * 50;
        int r = s * 64 + k;
        int c = idx & 15;
        int u = sIdx[s * 64 + k];
        const float4* src = (const float4*)(tbl + (size_t)u * 128 + c * 8);
        float4 v0 = src[0], v1 = src[1];
        __nv_bfloat16 h[8], lo[8];
        split1(v0.x, h[0], lo[0]); split1(v0.y, h[1], lo[1]);
        split1(v0.z, h[2], lo[2]); split1(v0.w, h[3], lo[3]);
        split1(v1.x, h[4], lo[4]); split1(v1.y, h[5], lo[5]);
        split1(v1.z, h[6], lo[6]); split1(v1.w, h[7], lo[7]);
        uint4 hv = make_uint4(pk2(h[0], h[1]), pk2(h[2], h[3]),
                              pk2(h[4], h[5]), pk2(h[6], h[7]));
        uint4 lv = make_uint4(pk2(lo[0], lo[1]), pk2(lo[2], lo[3]),
                              pk2(lo[4], lo[5]), pk2(lo[6], lo[7]));
        int off = tile_off(r, c);
        *(uint4*)(smemc + SM_AHI + off) = hv;
        *(uint4*)(smemc + SM_ALO + off) = lv;
    }
}

// bias + relu -> re-split to A tiles (opt: fp32 coup to gmem); resets acc
__device__ __forceinline__ void epilogueA(
    float (&acc)[16][4], char* smemc,
    const float* bias0, const float* bias1,
    float* coupBase, int w, int l)
{
    int q = 16 * w + (l >> 2);
    int p2 = (l & 3) * 2;
    const float* bA = (q < 64) ? bias0 : bias1;
    int r0 = q, r1 = q + 8;
#pragma unroll
    for (int t = 0; t < 16; ++t) {
        int n = 8 * t + p2;
        float y00 = fmaxf(acc[t][0] + bA[n],     0.f);
        float y01 = fmaxf(acc[t][1] + bA[n + 1], 0.f);
        float y10 = fmaxf(acc[t][2] + bA[n],     0.f);
        float y11 = fmaxf(acc[t][3] + bA[n + 1], 0.f);
        acc[t][0] = 0.f; acc[t][1] = 0.f; acc[t][2] = 0.f; acc[t][3] = 0.f;
        __nv_bfloat16 h0, l0, h1, l1;
        split1(y00, h0, l0); split1(y01, h1, l1);
        int o0 = tile_off(r0, t) + p2 * 2;
        *(uint32_t*)(smemc + SM_AHI + o0) = pk2(h0, h1);
        *(uint32_t*)(smemc + SM_ALO + o0) = pk2(l0, l1);
        split1(y10, h0, l0); split1(y11, h1, l1);
        int o1 = tile_off(r1, t) + p2 * 2;
        *(uint32_t*)(smemc + SM_AHI + o1) = pk2(h0, h1);
        *(uint32_t*)(smemc + SM_ALO + o1) = pk2(l0, l1);
        if (coupBase) {
            *(float2*)(coupBase + (size_t)r0 * 128 + n) = make_float2(y00, y01);
            *(float2*)(coupBase + (size_t)r1 * 128 + n) = make_float2(y10, y11);
        }
    }
}

// last layer: bias+relu, dot with w3, reduce quad -> sScore
__device__ __forceinline__ void epilogueScore(
    float (&acc)[16][4], const float* ba2, const float* w3, float b3,
    float* sScore, int w, int l)
{
    int q = 16 * w + (l >> 2);
    int p2 = (l & 3) * 2;
    float p0 = 0.f, p1 = 0.f;
#pragma unroll
    for (int t = 0; t < 16; ++t) {
        int n = 8 * t + p2;
        p0 = fmaf(fmaxf(acc[t][0] + ba2[n],     0.f), w3[n],     p0);
        p0 = fmaf(fmaxf(acc[t][1] + ba2[n + 1], 0.f), w3[n + 1], p0);
        p1 = fmaf(fmaxf(acc[t][2] + ba2[n],     0.f), w3[n],     p1);
        p1 = fmaf(fmaxf(acc[t][3] + ba2[n + 1], 0.f), w3[n + 1], p1);
    }
    p0 += __shfl_xor_sync(0xffffffffu, p0, 1);
    p0 += __shfl_xor_sync(0xffffffffu, p0, 2);
    p1 += __shfl_xor_sync(0xffffffffu, p1, 1);
    p1 += __shfl_xor_sync(0xffffffffu, p1, 2);
    if ((l & 3) == 0) {
        sScore[q]     = p0 + b3;
        sScore[q + 8] = p1 + b3;
    }
}

#define WAITG(n) asm volatile("cp.async.wait_group %0;" :: "n"(n) : "memory")

__global__ __launch_bounds__(256, 1)
void influence_main(
    const float* __restrict__ act_users_f,  // actually int*, cast below
    const float* __restrict__ emb_table, const float* __restrict__ prof_table,
    const float* __restrict__ b_fus, const float* __restrict__ b_c2,
    const float* __restrict__ b_a2,  const float* __restrict__ w_a3,
    const float* __restrict__ b_a3,
    int Btot,
    float* __restrict__ out_combined, float* __restrict__ out_att)
{
    extern __shared__ char smemc[];
    const int tid = threadIdx.x;
    const int w = tid >> 5, l = tid & 31;
    const int b0 = blockIdx.x * 2;
    const int* act_users = (const int*)act_users_f;
    uint32_t sb = smem_u32(smemc);

    int* sIdx     = (int*)(smemc + SM_IDX);
    float* sBfus  = (float*)(smemc + SM_BFUS);
    float* sBc2   = (float*)(smemc + SM_BC2);
    float* sBa2   = (float*)(smemc + SM_BA2);
    float* sW3    = (float*)(smemc + SM_W3);
    float* sVC1   = (float*)(smemc + SM_VC1);
    float* sVA1   = (float*)(smemc + SM_VA1);
    float* sScore = (float*)(smemc + SM_SCORE);
    float* sAtt   = (float*)(smemc + SM_ATT);
    float* coup   = g_coup + (size_t)blockIdx.x * 16384;

    // start weight pipeline: unit0 -> B0, unit1 -> B1
    copy_unit(0, sb + SM_B0H, tid);
    copy_unit(1, sb + SM_B1H, tid);

    if (tid < 100) {
        int s = tid / 50, k = tid - s * 50;
        sIdx[s * 64 + k] = act_users[(size_t)(b0 + s) * K_N + k];
    }
    if (tid < 128) {
        sBfus[tid] = b_fus[tid];
        sBc2[tid]  = b_c2[tid];
        sBa2[tid]  = b_a2[tid];
        sW3[tid]   = w_a3[tid];
    }
    if (tid >= 128 && tid < 256) {
        int c = tid - 128;
        sVC1[c]       = g_vec[(size_t)(b0 + 0) * 128 + c];
        sVC1[128 + c] = g_vec[(size_t)(b0 + 1) * 128 + c];
        sVA1[c]       = g_vec[(size_t)Btot * 128 + (size_t)(b0 + 0) * 128 + c];
        sVA1[128 + c] = g_vec[(size_t)Btot * 128 + (size_t)(b0 + 1) * 128 + c];
    }
    // zero pad rows (50-63, 114-127)
    for (int idx = tid; idx < 28 * 16; idx += 256) {
        int pr = idx >> 4;
        int r = (pr < 14) ? (50 + pr) : (100 + pr);
        int c = idx & 15;
        int off = tile_off(r, c);
        *(uint4*)(smemc + SM_AHI + off) = make_uint4(0, 0, 0, 0);
        *(uint4*)(smemc + SM_ALO + off) = make_uint4(0, 0, 0, 0);
    }
    __syncthreads();                       // sIdx visible
    gatherA(emb_table, sIdx, smemc, tid);

    float acc[16][4];
#pragma unroll
    for (int t = 0; t < 16; ++t) {
        acc[t][0] = 0.f; acc[t][1] = 0.f; acc[t][2] = 0.f; acc[t][3] = 0.f;
    }

    WAITG(1); __syncthreads();             // A(emb) + unit0 ready
    sweep(acc, sb + SM_AHI, sb + SM_ALO, sb + SM_B0H, sb + SM_B0L, w, l);
    __syncthreads();                       // B0 free
    copy_unit(2, sb + SM_B0H, tid);
    gatherA(prof_table, sIdx, smemc, tid); // rewrite A (pads stay zero)
    WAITG(1); __syncthreads();             // A(prof) + unit1 ready
    sweep(acc, sb + SM_AHI, sb + SM_ALO, sb + SM_B1H, sb + SM_B1L, w, l);
    __syncthreads();                       // B1 free
    copy_unit(3, sb + SM_B1H, tid);
    epilogueA(acc, smemc, sBfus, sBfus, nullptr, w, l);     // L1 -> fused
    WAITG(1); __syncthreads();
    sweep(acc, sb + SM_AHI, sb + SM_ALO, sb + SM_B0H, sb + SM_B0L, w, l);   // L2
    __syncthreads();
    copy_unit(4, sb + SM_B0H, tid);
    epilogueA(acc, smemc, sVC1, sVC1 + 128, nullptr, w, l); // L2 -> c1
    WAITG(1); __syncthreads();
    sweep(acc, sb + SM_AHI, sb + SM_ALO, sb + SM_B1H, sb + SM_B1L, w, l);   // L3
    __syncthreads();
    copy_unit(5, sb + SM_B1H, tid);
    epilogueA(acc, smemc, sBc2, sBc2, coup, w, l);          // L3 -> coup (+gmem)
    WAITG(1); __syncthreads();
    sweep(acc, sb + SM_AHI, sb + SM_ALO, sb + SM_B0H, sb + SM_B0L, w, l);   // L4
    __syncthreads();
    epilogueA(acc, smemc, sVA1, sVA1 + 128, nullptr, w, l); // L4 -> h
    WAITG(0); __syncthreads();
    sweep(acc, sb + SM_AHI, sb + SM_ALO, sb + SM_B1H, sb + SM_B1L, w, l);   // L5
    epilogueScore(acc, sBa2, sW3, b_a3[0], sScore, w, l);
    __syncthreads();

    // softmax per sample (warp 0 -> s0, warp 1 -> s1)
    if (w < 2) {
        int base = w * 64;
        float v1 = (l < K_N)      ? sScore[base + l]      : -1e30f;
        float v2 = (l + 32 < K_N) ? sScore[base + l + 32] : -1e30f;
        float m = fmaxf(v1, v2);
#pragma unroll
        for (int o = 16; o; o >>= 1)
            m = fmaxf(m, __shfl_xor_sync(0xffffffffu, m, o));
        float e1 = (l < K_N)      ? expf(v1 - m) : 0.f;
        float e2 = (l + 32 < K_N) ? expf(v2 - m) : 0.f;
        float sum = e1 + e2;
#pragma unroll
        for (int o = 16; o; o >>= 1)
            sum += __shfl_xor_sync(0xffffffffu, sum, o);
        float inv = 1.f / sum;
        if (l < K_N)      sAtt[base + l]      = e1 * inv;
        if (l + 32 < K_N) sAtt[base + l + 32] = e2 * inv;
    }
    __syncthreads();

    // combined[s][col] = sum_k att[s][k] * coup[s*64+k][col]
    {
        int s = tid >> 7, col = tid & 127;
        float a = 0.f;
#pragma unroll 2
        for (int k = 0; k < K_N; ++k)
            a = fmaf(sAtt[s * 64 + k], coup[(size_t)(s * 64 + k) * 128 + col], a);
        out_combined[(size_t)(b0 + s) * 128 + col] = a;
    }
    if (tid < 2 * K_N) {
        int s = tid / K_N, k = tid - s * K_N;
        out_att[(size_t)(b0 + s) * K_N + k] = sAtt[s * 64 + k];
    }
}

// ---------------- host launcher ----------------
extern "C" void kernel_launch(void* const* d_in, const int* in_sizes, int n_in,
                              void* d_out, int out_size) {
    const float* u_embs = (const float*)d_in[1];
    const float* i_embs = (const float*)d_in[3];
    const float* act    = (const float*)d_in[4];   // int32 data
    const float* table  = (const float*)d_in[5];
    const float* prof   = (const float*)d_in[6];
    const float* w_fus  = (const float*)d_in[7];
    const float* b_fus  = (const float*)d_in[8];
    const float* w_c1   = (const float*)d_in[9];
    const float* b_c1   = (const float*)d_in[10];
    const float* w_c2   = (const float*)d_in[11];
    const float* b_c2   = (const float*)d_in[12];
    const float* w_a1   = (const float*)d_in[13];
    const float* b_a1   = (const float*)d_in[14];
    const float* w_a2   = (const float*)d_in[15];
    const float* b_a2   = (const float*)d_in[16];
    const float* w_a3   = (const float*)d_in[17];
    const float* b_a3   = (const float*)d_in[18];

    int B = in_sizes[0];   // 4096

    float* out_combined = (float*)d_out;
    float* out_att      = out_combined + (size_t)B * 128;

    prep_weights<<<48, 256>>>(w_fus, w_c1, w_c2, w_a1, w_a2);
    prep_vecs<<<dim3(B, 2), 128>>>(i_embs, u_embs, w_c1, b_c1, w_a1, b_a1, B);

    cudaFuncSetAttribute(influence_main,
                         cudaFuncAttributeMaxDynamicSharedMemorySize, SM_TOTAL);
    influence_main<<<B / 2, 256, SM_TOTAL>>>(
        act, table, prof,
        b_fus, b_c2, b_a2, w_a3, b_a3, B,
        out_combined, out_att);
}

// round 8
// speedup vs baseline: 1.9319x; 1.2030x over previous
#include <cuda_runtime.h>
#include <cuda_fp16.h>
#include <cstdint>

// InfluenceProp R8: HMMA fp16 2-term split.
// A (activations) = Ahi + Alo fp16 (exact to ~2^-22); B (weights) = single
// fp16-rn. D = Ahi*B + Alo*B, fp32 accumulate. Only error is A*(B - fp16(B))
// ~2^-12 relative per layer. MMA count drops 48->32 per k-step vs R7, B smem
// and copy traffic halve.

#define K_N 50

// ---------------- gmem scratch ----------------
__device__ __align__(1024) __half g_wb[6 * 16384];   // 6 units x 128x128 fp16 (hi only)
__device__ float g_vec[2ull * 4096 * 128];           // folded biases [which][b][128]
__device__ float g_coup[2048ull * 128 * 128];        // per-CTA coup fp32

// ---------------- smem byte offsets ----------------
#define SM_AHI   0
#define SM_ALO   32768
#define SM_B0    65536
#define SM_B1    98304
#define SM_IDX   131072
#define SM_BFUS  131584
#define SM_BC2   132096
#define SM_BA2   132608
#define SM_W3    133120
#define SM_VC1   133632
#define SM_VA1   134656
#define SM_SCORE 135680
#define SM_ATT   136192
#define SM_TOTAL 136704

// tile layout: row r (0-127), 256 B/row; 16B chunk c stored at (c ^ (r&7))
__device__ __host__ __forceinline__ int tile_off(int r, int c) {
    return r * 256 + ((c ^ (r & 7)) << 4);
}

__device__ __forceinline__ uint32_t smem_u32(const void* p) {
    uint32_t a;
    asm("{ .reg .u64 t; cvta.to.shared.u64 t, %1; cvt.u32.u64 %0, t; }" : "=r"(a) : "l"(p));
    return a;
}

#define LDSM4(r0, r1, r2, r3, addr) \
    asm volatile("ldmatrix.sync.aligned.m8n8.x4.shared.b16 {%0,%1,%2,%3}, [%4];" \
                 : "=r"(r0), "=r"(r1), "=r"(r2), "=r"(r3) : "r"(addr))
#define MMA(ac, a0, a1, a2, a3, b0, b1) \
    asm volatile("mma.sync.aligned.m16n8k16.row.col.f32.f16.f16.f32 " \
                 "{%0,%1,%2,%3},{%4,%5,%6,%7},{%8,%9},{%0,%1,%2,%3};" \
                 : "+f"((ac)[0]), "+f"((ac)[1]), "+f"((ac)[2]), "+f"((ac)[3]) \
                 : "r"(a0), "r"(a1), "r"(a2), "r"(a3), "r"(b0), "r"(b1))

__device__ __forceinline__ uint32_t pk2(__half lo, __half hi) {
    return (uint32_t)__half_as_ushort(hi) << 16 | __half_as_ushort(lo);
}
__device__ __forceinline__ void split1(float x, __half& h, __half& l) {
    h = __float2half_rn(x);
    l = __float2half_rn(x - __half2float(h));
}

// ---------------- prepass 1: weight fp16 + transpose + swizzle ----------------
__global__ void prep_weights(
    const float* __restrict__ w_fus, const float* __restrict__ w_c1,
    const float* __restrict__ w_c2,  const float* __restrict__ w_a1,
    const float* __restrict__ w_a2)
{
    int u = blockIdx.x >> 3;            // 6 units x 8 parts
    int part = blockIdx.x & 7;
    const float* base; int koff = 0;
    if      (u == 0) { base = w_fus; }
    else if (u == 1) { base = w_fus; koff = 128; }
    else if (u == 2) { base = w_c1; }
    else if (u == 3) { base = w_c2; }
    else if (u == 4) { base = w_a1; }
    else             { base = w_a2; }

    int e0 = part * 2048;
    for (int i = threadIdx.x; i < 2048; i += blockDim.x) {
        int e = e0 + i;
        int n = e >> 7, k = e & 127;
        float v = base[(size_t)(k + koff) * 128 + n];
        int elem = (n * 256 + (((k >> 3) ^ (n & 7)) << 4) + (k & 7) * 2) >> 1;
        g_wb[(size_t)u * 16384 + elem] = __float2half_rn(v);
    }
}

// ---------------- prepass 2: folded per-sample bias vectors ----------------
__global__ void prep_vecs(
    const float* __restrict__ i_embs, const float* __restrict__ u_embs,
    const float* __restrict__ w_c1,   const float* __restrict__ b_c1,
    const float* __restrict__ w_a1,   const float* __restrict__ b_a1,
    int Btot)
{
    int b = blockIdx.x;
    int which = blockIdx.y;
    int col = threadIdx.x;
    const float* emb = which ? u_embs : i_embs;
    const float* W   = (which ? w_a1 : w_c1) + (size_t)128 * 128;
    const float* bb  = which ? b_a1 : b_c1;
    float acc = bb[col];
#pragma unroll 4
    for (int i = 0; i < 128; ++i)
        acc = fmaf(emb[(size_t)b * 128 + i], W[(size_t)i * 128 + col], acc);
    g_vec[(size_t)which * Btot * 128 + (size_t)b * 128 + col] = acc;
}

// ---------------- main kernel pieces ----------------
__device__ __forceinline__ void copy_unit(int u, uint32_t dstAddr, int tid) {
    const char* src = (const char*)g_wb + (size_t)u * 32768;
#pragma unroll
    for (int t = 0; t < 8; ++t) {
        int i = tid + t * 256;             // 0..2047 16B lines
        asm volatile("cp.async.cg.shared.global [%0], [%1], 16;"
                     :: "r"(dstAddr + i * 16), "l"(src + (size_t)i * 16));
    }
    asm volatile("cp.async.commit_group;" ::: "memory");
}

// 2-term sweep: acc += Ahi*B + Alo*B  over K=128
__device__ __forceinline__ void sweep(
    float (&acc)[16][4],
    uint32_t aHi, uint32_t aLo, uint32_t bB,
    int w, int l)
{
    const int rA = 16 * w + (l & 15);
    const uint32_t aRowOff = (uint32_t)rA * 256;
    const int axor = rA & 7;
    const int khA = l >> 4;
    // B x4 addressing: lane l -> tile-pair member (l>>4)&1, row l&7, khalf (l>>3)&1
    const uint32_t bLane = (uint32_t)(((l >> 4) & 1) * 2048 + (l & 7) * 256);
    const int bKh  = (l >> 3) & 1;
    const int bxor = l & 7;

#pragma unroll 1
    for (int ks = 0; ks < 8; ++ks) {
        uint32_t aoff = aRowOff + (uint32_t)(((2 * ks + khA) ^ axor) << 4);
        uint32_t ah0, ah1, ah2, ah3, al0, al1, al2, al3;
        LDSM4(ah0, ah1, ah2, ah3, aHi + aoff);
        LDSM4(al0, al1, al2, al3, aLo + aoff);

        uint32_t bko = bLane + (uint32_t)(((2 * ks + bKh) ^ bxor) << 4);

        // load all 16 B fragments (8 tile-pair LDSM4)
        uint32_t bh[16][2];
#pragma unroll
        for (int p = 0; p < 8; ++p)
            LDSM4(bh[2 * p][0], bh[2 * p][1], bh[2 * p + 1][0], bh[2 * p + 1][1],
                  bB + (uint32_t)p * 4096 + bko);

        // pass 1: Ahi x B  (16 independent MMAs)
#pragma unroll
        for (int t = 0; t < 16; ++t)
            MMA(acc[t], ah0, ah1, ah2, ah3, bh[t][0], bh[t][1]);
        // pass 2: Alo x B  (reuse held B fragments)
#pragma unroll
        for (int t = 0; t < 16; ++t)
            MMA(acc[t], al0, al1, al2, al3, bh[t][0], bh[t][1]);
    }
}

// gather table rows -> split -> swizzled A tiles (rows s*64+k)
__device__ __forceinline__ void gatherA(
    const float* __restrict__ tbl, const int* sIdx, char* smemc, int tid)
{
    for (int idx = tid; idx < 1600; idx += 256) {
        int rowi = idx >> 4;                  // 0..99
        int s = (rowi >= 50) ? 1 : 0;
        int k = rowi - s * 50;
        int r = s * 64 + k;
        int c = idx & 15;
        int u = sIdx[s * 64 + k];
        const float4* src = (const float4*)(tbl + (size_t)u * 128 + c * 8);
        float4 v0 = src[0], v1 = src[1];
        __half h[8], lo[8];
        split1(v0.x, h[0], lo[0]); split1(v0.y, h[1], lo[1]);
        split1(v0.z, h[2], lo[2]); split1(v0.w, h[3], lo[3]);
        split1(v1.x, h[4], lo[4]); split1(v1.y, h[5], lo[5]);
        split1(v1.z, h[6], lo[6]); split1(v1.w, h[7], lo[7]);
        uint4 hv = make_uint4(pk2(h[0], h[1]), pk2(h[2], h[3]),
                              pk2(h[4], h[5]), pk2(h[6], h[7]));
        uint4 lv = make_uint4(pk2(lo[0], lo[1]), pk2(lo[2], lo[3]),
                              pk2(lo[4], lo[5]), pk2(lo[6], lo[7]));
        int off = tile_off(r, c);
        *(uint4*)(smemc + SM_AHI + off) = hv;
        *(uint4*)(smemc + SM_ALO + off) = lv;
    }
}

// bias + relu -> re-split to A tiles (opt: fp32 coup to gmem); resets acc
__device__ __forceinline__ void epilogueA(
    float (&acc)[16][4], char* smemc,
    const float* bias0, const float* bias1,
    float* coupBase, int w, int l)
{
    int q = 16 * w + (l >> 2);
    int p2 = (l & 3) * 2;
    const float* bA = (q < 64) ? bias0 : bias1;
    int r0 = q, r1 = q + 8;
#pragma unroll
    for (int t = 0; t < 16; ++t) {
        int n = 8 * t + p2;
        float y00 = fmaxf(acc[t][0] + bA[n],     0.f);
        float y01 = fmaxf(acc[t][1] + bA[n + 1], 0.f);
        float y10 = fmaxf(acc[t][2] + bA[n],     0.f);
        float y11 = fmaxf(acc[t][3] + bA[n + 1], 0.f);
        acc[t][0] = 0.f; acc[t][1] = 0.f; acc[t][2] = 0.f; acc[t][3] = 0.f;
        __half h0, l0, h1, l1;
        split1(y00, h0, l0); split1(y01, h1, l1);
        int o0 = tile_off(r0, t) + p2 * 2;
        *(uint32_t*)(smemc + SM_AHI + o0) = pk2(h0, h1);
        *(uint32_t*)(smemc + SM_ALO + o0) = pk2(l0, l1);
        split1(y10, h0, l0); split1(y11, h1, l1);
        int o1 = tile_off(r1, t) + p2 * 2;
        *(uint32_t*)(smemc + SM_AHI + o1) = pk2(h0, h1);
        *(uint32_t*)(smemc + SM_ALO + o1) = pk2(l0, l1);
        if (coupBase) {
            *(float2*)(coupBase + (size_t)r0 * 128 + n) = make_float2(y00, y01);
            *(float2*)(coupBase + (size_t)r1 * 128 + n) = make_float2(y10, y11);
        }
    }
}

// last layer: bias+relu, dot with w3, reduce quad -> sScore
__device__ __forceinline__ void epilogueScore(
    float (&acc)[16][4], const float* ba2, const float* w3, float b3,
    float* sScore, int w, int l)
{
    int q = 16 * w + (l >> 2);
    int p2 = (l & 3) * 2;
    float p0 = 0.f, p1 = 0.f;
#pragma unroll
    for (int t = 0; t < 16; ++t) {
        int n = 8 * t + p2;
        p0 = fmaf(fmaxf(acc[t][0] + ba2[n],     0.f), w3[n],     p0);
        p0 = fmaf(fmaxf(acc[t][1] + ba2[n + 1], 0.f), w3[n + 1], p0);
        p1 = fmaf(fmaxf(acc[t][2] + ba2[n],     0.f), w3[n],     p1);
        p1 = fmaf(fmaxf(acc[t][3] + ba2[n + 1], 0.f), w3[n + 1], p1);
    }
    p0 += __shfl_xor_sync(0xffffffffu, p0, 1);
    p0 += __shfl_xor_sync(0xffffffffu, p0, 2);
    p1 += __shfl_xor_sync(0xffffffffu, p1, 1);
    p1 += __shfl_xor_sync(0xffffffffu, p1, 2);
    if ((l & 3) == 0) {
        sScore[q]     = p0 + b3;
        sScore[q + 8] = p1 + b3;
    }
}

#define WAITG(n) asm volatile("cp.async.wait_group %0;" :: "n"(n) : "memory")

__global__ __launch_bounds__(256, 1)
void influence_main(
    const float* __restrict__ act_users_f,  // actually int*, cast below
    const float* __restrict__ emb_table, const float* __restrict__ prof_table,
    const float* __restrict__ b_fus, const float* __restrict__ b_c2,
    const float* __restrict__ b_a2,  const float* __restrict__ w_a3,
    const float* __restrict__ b_a3,
    int Btot,
    float* __restrict__ out_combined, float* __restrict__ out_att)
{
    extern __shared__ char smemc[];
    const int tid = threadIdx.x;
    const int w = tid >> 5, l = tid & 31;
    const int b0 = blockIdx.x * 2;
    const int* act_users = (const int*)act_users_f;
    uint32_t sb = smem_u32(smemc);

    int* sIdx     = (int*)(smemc + SM_IDX);
    float* sBfus  = (float*)(smemc + SM_BFUS);
    float* sBc2   = (float*)(smemc + SM_BC2);
    float* sBa2   = (float*)(smemc + SM_BA2);
    float* sW3    = (float*)(smemc + SM_W3);
    float* sVC1   = (float*)(smemc + SM_VC1);
    float* sVA1   = (float*)(smemc + SM_VA1);
    float* sScore = (float*)(smemc + SM_SCORE);
    float* sAtt   = (float*)(smemc + SM_ATT);
    float* coup   = g_coup + (size_t)blockIdx.x * 16384;

    // start weight pipeline: unit0 -> B0, unit1 -> B1
    copy_unit(0, sb + SM_B0, tid);
    copy_unit(1, sb + SM_B1, tid);

    if (tid < 100) {
        int s = tid / 50, k = tid - s * 50;
        sIdx[s * 64 + k] = act_users[(size_t)(b0 + s) * K_N + k];
    }
    if (tid < 128) {
        sBfus[tid] = b_fus[tid];
        sBc2[tid]  = b_c2[tid];
        sBa2[tid]  = b_a2[tid];
        sW3[tid]   = w_a3[tid];
    }
    if (tid >= 128 && tid < 256) {
        int c = tid - 128;
        sVC1[c]       = g_vec[(size_t)(b0 + 0) * 128 + c];
        sVC1[128 + c] = g_vec[(size_t)(b0 + 1) * 128 + c];
        sVA1[c]       = g_vec[(size_t)Btot * 128 + (size_t)(b0 + 0) * 128 + c];
        sVA1[128 + c] = g_vec[(size_t)Btot * 128 + (size_t)(b0 + 1) * 128 + c];
    }
    // zero pad rows (50-63, 114-127)
    for (int idx = tid; idx < 28 * 16; idx += 256) {
        int pr = idx >> 4;
        int r = (pr < 14) ? (50 + pr) : (100 + pr);
        int c = idx & 15;
        int off = tile_off(r, c);
        *(uint4*)(smemc + SM_AHI + off) = make_uint4(0, 0, 0, 0);
        *(uint4*)(smemc + SM_ALO + off) = make_uint4(0, 0, 0, 0);
    }
    __syncthreads();                       // sIdx visible
    gatherA(emb_table, sIdx, smemc, tid);

    float acc[16][4];
#pragma unroll
    for (int t = 0; t < 16; ++t) {
        acc[t][0] = 0.f; acc[t][1] = 0.f; acc[t][2] = 0.f; acc[t][3] = 0.f;
    }

    WAITG(1); __syncthreads();             // A(emb) + unit0 ready
    sweep(acc, sb + SM_AHI, sb + SM_ALO, sb + SM_B0, w, l);
    __syncthreads();                       // B0 free
    copy_unit(2, sb + SM_B0, tid);
    gatherA(prof_table, sIdx, smemc, tid); // rewrite A (pads stay zero)
    WAITG(1); __syncthreads();             // A(prof) + unit1 ready
    sweep(acc, sb + SM_AHI, sb + SM_ALO, sb + SM_B1, w, l);
    __syncthreads();                       // B1 free
    copy_unit(3, sb + SM_B1, tid);
    epilogueA(acc, smemc, sBfus, sBfus, nullptr, w, l);     // L1 -> fused
    WAITG(1); __syncthreads();
    sweep(acc, sb + SM_AHI, sb + SM_ALO, sb + SM_B0, w, l);   // L2
    __syncthreads();
    copy_unit(4, sb + SM_B0, tid);
    epilogueA(acc, smemc, sVC1, sVC1 + 128, nullptr, w, l); // L2 -> c1
    WAITG(1); __syncthreads();
    sweep(acc, sb + SM_AHI, sb + SM_ALO, sb + SM_B1, w, l);   // L3
    __syncthreads();
    copy_unit(5, sb + SM_B1, tid);
    epilogueA(acc, smemc, sBc2, sBc2, coup, w, l);          // L3 -> coup (+gmem)
    WAITG(1); __syncthreads();
    sweep(acc, sb + SM_AHI, sb + SM_ALO, sb + SM_B0, w, l);   // L4
    __syncthreads();
    epilogueA(acc, smemc, sVA1, sVA1 + 128, nullptr, w, l); // L4 -> h
    WAITG(0); __syncthreads();
    sweep(acc, sb + SM_AHI, sb + SM_ALO, sb + SM_B1, w, l);   // L5
    epilogueScore(acc, sBa2, sW3, b_a3[0], sScore, w, l);
    __syncthreads();

    // softmax per sample (warp 0 -> s0, warp 1 -> s1)
    if (w < 2) {
        int base = w * 64;
        float v1 = (l < K_N)      ? sScore[base + l]      : -1e30f;
        float v2 = (l + 32 < K_N) ? sScore[base + l + 32] : -1e30f;
        float m = fmaxf(v1, v2);
#pragma unroll
        for (int o = 16; o; o >>= 1)
            m = fmaxf(m, __shfl_xor_sync(0xffffffffu, m, o));
        float e1 = (l < K_N)      ? expf(v1 - m) : 0.f;
        float e2 = (l + 32 < K_N) ? expf(v2 - m) : 0.f;
        float sum = e1 + e2;
#pragma unroll
        for (int o = 16; o; o >>= 1)
            sum += __shfl_xor_sync(0xffffffffu, sum, o);
        float inv = 1.f / sum;
        if (l < K_N)      sAtt[base + l]      = e1 * inv;
        if (l + 32 < K_N) sAtt[base + l + 32] = e2 * inv;
    }
    __syncthreads();

    // combined[s][col] = sum_k att[s][k] * coup[s*64+k][col]
    {
        int s = tid >> 7, col = tid & 127;
        float a = 0.f;
#pragma unroll 2
        for (int k = 0; k < K_N; ++k)
            a = fmaf(sAtt[s * 64 + k], coup[(size_t)(s * 64 + k) * 128 + col], a);
        out_combined[(size_t)(b0 + s) * 128 + col] = a;
    }
    if (tid < 2 * K_N) {
        int s = tid / K_N, k = tid - s * K_N;
        out_att[(size_t)(b0 + s) * K_N + k] = sAtt[s * 64 + k];
    }
}

// ---------------- host launcher ----------------
extern "C" void kernel_launch(void* const* d_in, const int* in_sizes, int n_in,
                              void* d_out, int out_size) {
    const float* u_embs = (const float*)d_in[1];
    const float* i_embs = (const float*)d_in[3];
    const float* act    = (const float*)d_in[4];   // int32 data
    const float* table  = (const float*)d_in[5];
    const float* prof   = (const float*)d_in[6];
    const float* w_fus  = (const float*)d_in[7];
    const float* b_fus  = (const float*)d_in[8];
    const float* w_c1   = (const float*)d_in[9];
    const float* b_c1   = (const float*)d_in[10];
    const float* w_c2   = (const float*)d_in[11];
    const float* b_c2   = (const float*)d_in[12];
    const float* w_a1   = (const float*)d_in[13];
    const float* b_a1   = (const float*)d_in[14];
    const float* w_a2   = (const float*)d_in[15];
    const float* b_a2   = (const float*)d_in[16];
    const float* w_a3   = (const float*)d_in[17];
    const float* b_a3   = (const float*)d_in[18];

    int B = in_sizes[0];   // 4096

    float* out_combined = (float*)d_out;
    float* out_att      = out_combined + (size_t)B * 128;

    prep_weights<<<48, 256>>>(w_fus, w_c1, w_c2, w_a1, w_a2);
    prep_vecs<<<dim3(B, 2), 128>>>(i_embs, u_embs, w_c1, b_c1, w_a1, b_a1, B);

    cudaFuncSetAttribute(influence_main,
                         cudaFuncAttributeMaxDynamicSharedMemorySize, SM_TOTAL);
    influence_main<<<B / 2, 256, SM_TOTAL>>>(
        act, table, prof,
        b_fus, b_c2, b_a2, w_a3, b_a3, B,
        out_combined, out_att);
}

// round 9
// speedup vs baseline: 2.5941x; 1.3428x over previous
#include <cuda_runtime.h>
#include <cuda_fp16.h>
#include <cstdint>

// InfluenceProp R9: R8's fp16 2-term HMMA math, restructured to 1 sample/CTA
// (M=64, smem ~100KB) so 2 CTAs co-reside per SM and overlap each other's
// epilogue/gather/barrier bubbles. 8 warps = 2 n-halves x 4 row-quarters.

#define K_N 50

// ---------------- gmem scratch ----------------
__device__ __align__(1024) __half g_wb[6 * 16384];   // 6 units x 128x128 fp16
__device__ float g_vec[2ull * 4096 * 128];           // folded biases [which][b][128]
__device__ float g_coup[4096ull * 8192];             // per-CTA coup fp32 [64][128]

// ---------------- smem byte offsets ----------------
#define SM_AHI   0          // 64x128 fp16 swizzled (16KB)
#define SM_ALO   16384
#define SM_B0    32768      // 128x128 fp16 (32KB)
#define SM_B1    65536
#define SM_IDX   98304
#define SM_BFUS  98560
#define SM_BC2   99072
#define SM_BA2   99584
#define SM_W3    100096
#define SM_VC1   100608
#define SM_VA1   101120
#define SM_SCORE 101632     // [2][64] partial scores
#define SM_ATT   102144
#define SM_TOTAL 102400

// tile layout: row r, 256 B/row; 16B chunk c stored at (c ^ (r&7))
__device__ __host__ __forceinline__ int tile_off(int r, int c) {
    return r * 256 + ((c ^ (r & 7)) << 4);
}

__device__ __forceinline__ uint32_t smem_u32(const void* p) {
    uint32_t a;
    asm("{ .reg .u64 t; cvta.to.shared.u64 t, %1; cvt.u32.u64 %0, t; }" : "=r"(a) : "l"(p));
    return a;
}

#define LDSM4(r0, r1, r2, r3, addr) \
    asm volatile("ldmatrix.sync.aligned.m8n8.x4.shared.b16 {%0,%1,%2,%3}, [%4];" \
                 : "=r"(r0), "=r"(r1), "=r"(r2), "=r"(r3) : "r"(addr))
#define MMA(ac, a0, a1, a2, a3, b0, b1) \
    asm volatile("mma.sync.aligned.m16n8k16.row.col.f32.f16.f16.f32 " \
                 "{%0,%1,%2,%3},{%4,%5,%6,%7},{%8,%9},{%0,%1,%2,%3};" \
                 : "+f"((ac)[0]), "+f"((ac)[1]), "+f"((ac)[2]), "+f"((ac)[3]) \
                 : "r"(a0), "r"(a1), "r"(a2), "r"(a3), "r"(b0), "r"(b1))

__device__ __forceinline__ uint32_t pk2(__half lo, __half hi) {
    return (uint32_t)__half_as_ushort(hi) << 16 | __half_as_ushort(lo);
}
__device__ __forceinline__ void split1(float x, __half& h, __half& l) {
    h = __float2half_rn(x);
    l = __float2half_rn(x - __half2float(h));
}

// ---------------- prepass 1: weight fp16 + transpose + swizzle ----------------
__global__ void prep_weights(
    const float* __restrict__ w_fus, const float* __restrict__ w_c1,
    const float* __restrict__ w_c2,  const float* __restrict__ w_a1,
    const float* __restrict__ w_a2)
{
    int u = blockIdx.x >> 3;
    int part = blockIdx.x & 7;
    const float* base; int koff = 0;
    if      (u == 0) { base = w_fus; }
    else if (u == 1) { base = w_fus; koff = 128; }
    else if (u == 2) { base = w_c1; }
    else if (u == 3) { base = w_c2; }
    else if (u == 4) { base = w_a1; }
    else             { base = w_a2; }

    int e0 = part * 2048;
    for (int i = threadIdx.x; i < 2048; i += blockDim.x) {
        int e = e0 + i;
        int n = e >> 7, k = e & 127;
        float v = base[(size_t)(k + koff) * 128 + n];
        int elem = (n * 256 + (((k >> 3) ^ (n & 7)) << 4) + (k & 7) * 2) >> 1;
        g_wb[(size_t)u * 16384 + elem] = __float2half_rn(v);
    }
}

// ---------------- prepass 2: folded per-sample bias vectors ----------------
__global__ void prep_vecs(
    const float* __restrict__ i_embs, const float* __restrict__ u_embs,
    const float* __restrict__ w_c1,   const float* __restrict__ b_c1,
    const float* __restrict__ w_a1,   const float* __restrict__ b_a1,
    int Btot)
{
    int b = blockIdx.x;
    int which = blockIdx.y;
    int col = threadIdx.x;
    const float* emb = which ? u_embs : i_embs;
    const float* W   = (which ? w_a1 : w_c1) + (size_t)128 * 128;
    const float* bb  = which ? b_a1 : b_c1;
    float acc = bb[col];
#pragma unroll 4
    for (int i = 0; i < 128; ++i)
        acc = fmaf(emb[(size_t)b * 128 + i], W[(size_t)i * 128 + col], acc);
    g_vec[(size_t)which * Btot * 128 + (size_t)b * 128 + col] = acc;
}

// ---------------- main kernel pieces ----------------
__device__ __forceinline__ void copy_unit(int u, uint32_t dstAddr, int tid) {
    const char* src = (const char*)g_wb + (size_t)u * 32768;
#pragma unroll
    for (int t = 0; t < 8; ++t) {
        int i = tid + t * 256;             // 0..2047 16B lines
        asm volatile("cp.async.cg.shared.global [%0], [%1], 16;"
                     :: "r"(dstAddr + i * 16), "l"(src + (size_t)i * 16));
    }
    asm volatile("cp.async.commit_group;" ::: "memory");
}

// 2-term sweep over K=128: warp (wg, wr) computes rows [16wr,16wr+16) x
// cols [64wg, 64wg+64). acc[8][4].
__device__ __forceinline__ void sweep(
    float (&acc)[8][4],
    uint32_t aHi, uint32_t aLo, uint32_t bB,
    int wg, int wr, int l)
{
    const int rA = 16 * wr + (l & 15);
    const uint32_t aRowOff = (uint32_t)rA * 256;
    const int axor = rA & 7;
    const int khA = l >> 4;
    const uint32_t bLane = (uint32_t)(((l >> 4) & 1) * 2048 + (l & 7) * 256);
    const int bKh  = (l >> 3) & 1;
    const int bxor = l & 7;
    const uint32_t bGrp = (uint32_t)wg * 16384;   // tiles 8wg..8wg+7

#pragma unroll 1
    for (int ks = 0; ks < 8; ++ks) {
        uint32_t aoff = aRowOff + (uint32_t)(((2 * ks + khA) ^ axor) << 4);
        uint32_t ah0, ah1, ah2, ah3, al0, al1, al2, al3;
        LDSM4(ah0, ah1, ah2, ah3, aHi + aoff);
        LDSM4(al0, al1, al2, al3, aLo + aoff);

        uint32_t bko = bGrp + bLane + (uint32_t)(((2 * ks + bKh) ^ bxor) << 4);

        uint32_t bh[8][2];
#pragma unroll
        for (int p = 0; p < 4; ++p)
            LDSM4(bh[2 * p][0], bh[2 * p][1], bh[2 * p + 1][0], bh[2 * p + 1][1],
                  bB + (uint32_t)p * 4096 + bko);

#pragma unroll
        for (int t = 0; t < 8; ++t)
            MMA(acc[t], ah0, ah1, ah2, ah3, bh[t][0], bh[t][1]);
#pragma unroll
        for (int t = 0; t < 8; ++t)
            MMA(acc[t], al0, al1, al2, al3, bh[t][0], bh[t][1]);
    }
}

// gather table rows -> split -> swizzled A tiles (rows 0..49)
__device__ __forceinline__ void gatherA(
    const float* __restrict__ tbl, const int* sIdx, char* smemc, int tid)
{
    for (int idx = tid; idx < 800; idx += 256) {
        int r = idx >> 4;                 // 0..49
        int c = idx & 15;
        int u = sIdx[r];
        const float4* src = (const float4*)(tbl + (size_t)u * 128 + c * 8);
        float4 v0 = src[0], v1 = src[1];
        __half h[8], lo[8];
        split1(v0.x, h[0], lo[0]); split1(v0.y, h[1], lo[1]);
        split1(v0.z, h[2], lo[2]); split1(v0.w, h[3], lo[3]);
        split1(v1.x, h[4], lo[4]); split1(v1.y, h[5], lo[5]);
        split1(v1.z, h[6], lo[6]); split1(v1.w, h[7], lo[7]);
        uint4 hv = make_uint4(pk2(h[0], h[1]), pk2(h[2], h[3]),
                              pk2(h[4], h[5]), pk2(h[6], h[7]));
        uint4 lv = make_uint4(pk2(lo[0], lo[1]), pk2(lo[2], lo[3]),
                              pk2(lo[4], lo[5]), pk2(lo[6], lo[7]));
        int off = tile_off(r, c);
        *(uint4*)(smemc + SM_AHI + off) = hv;
        *(uint4*)(smemc + SM_ALO + off) = lv;
    }
}

// bias + relu -> re-split into A tile chunks [8wg,8wg+8) (opt: coup); resets acc
__device__ __forceinline__ void epilogueA(
    float (&acc)[8][4], char* smemc, const float* bias,
    float* coupBase, int wg, int wr, int l)
{
    int q  = 16 * wr + (l >> 2);
    int p2 = (l & 3) * 2;
    int r0 = q, r1 = q + 8;
#pragma unroll
    for (int t = 0; t < 8; ++t) {
        int n = 64 * wg + 8 * t + p2;
        float y00 = fmaxf(acc[t][0] + bias[n],     0.f);
        float y01 = fmaxf(acc[t][1] + bias[n + 1], 0.f);
        float y10 = fmaxf(acc[t][2] + bias[n],     0.f);
        float y11 = fmaxf(acc[t][3] + bias[n + 1], 0.f);
        acc[t][0] = 0.f; acc[t][1] = 0.f; acc[t][2] = 0.f; acc[t][3] = 0.f;
        __half h0, l0, h1, l1;
        split1(y00, h0, l0); split1(y01, h1, l1);
        int o0 = tile_off(r0, 8 * wg + t) + p2 * 2;
        *(uint32_t*)(smemc + SM_AHI + o0) = pk2(h0, h1);
        *(uint32_t*)(smemc + SM_ALO + o0) = pk2(l0, l1);
        split1(y10, h0, l0); split1(y11, h1, l1);
        int o1 = tile_off(r1, 8 * wg + t) + p2 * 2;
        *(uint32_t*)(smemc + SM_AHI + o1) = pk2(h0, h1);
        *(uint32_t*)(smemc + SM_ALO + o1) = pk2(l0, l1);
        if (coupBase) {
            *(float2*)(coupBase + (size_t)r0 * 128 + n) = make_float2(y00, y01);
            *(float2*)(coupBase + (size_t)r1 * 128 + n) = make_float2(y10, y11);
        }
    }
}

// last layer: bias+relu, partial dot with w3 over this warp's n-half
__device__ __forceinline__ void epilogueScore(
    float (&acc)[8][4], const float* ba2, const float* w3,
    float* sScore, int wg, int wr, int l)
{
    int q  = 16 * wr + (l >> 2);
    int p2 = (l & 3) * 2;
    float p0 = 0.f, p1 = 0.f;
#pragma unroll
    for (int t = 0; t < 8; ++t) {
        int n = 64 * wg + 8 * t + p2;
        p0 = fmaf(fmaxf(acc[t][0] + ba2[n],     0.f), w3[n],     p0);
        p0 = fmaf(fmaxf(acc[t][1] + ba2[n + 1], 0.f), w3[n + 1], p0);
        p1 = fmaf(fmaxf(acc[t][2] + ba2[n],     0.f), w3[n],     p1);
        p1 = fmaf(fmaxf(acc[t][3] + ba2[n + 1], 0.f), w3[n + 1], p1);
    }
    p0 += __shfl_xor_sync(0xffffffffu, p0, 1);
    p0 += __shfl_xor_sync(0xffffffffu, p0, 2);
    p1 += __shfl_xor_sync(0xffffffffu, p1, 1);
    p1 += __shfl_xor_sync(0xffffffffu, p1, 2);
    if ((l & 3) == 0) {
        sScore[wg * 64 + q]     = p0;
        sScore[wg * 64 + q + 8] = p1;
    }
}

#define WAITG(n) asm volatile("cp.async.wait_group %0;" :: "n"(n) : "memory")

__global__ __launch_bounds__(256, 2)
void influence_main(
    const float* __restrict__ act_users_f,
    const float* __restrict__ emb_table, const float* __restrict__ prof_table,
    const float* __restrict__ b_fus, const float* __restrict__ b_c2,
    const float* __restrict__ b_a2,  const float* __restrict__ w_a3,
    const float* __restrict__ b_a3,
    int Btot,
    float* __restrict__ out_combined, float* __restrict__ out_att)
{
    extern __shared__ char smemc[];
    const int tid = threadIdx.x;
    const int w = tid >> 5, l = tid & 31;
    const int wg = w >> 2, wr = w & 3;
    const int b = blockIdx.x;
    const int* act_users = (const int*)act_users_f;
    uint32_t sb = smem_u32(smemc);

    int* sIdx     = (int*)(smemc + SM_IDX);
    float* sBfus  = (float*)(smemc + SM_BFUS);
    float* sBc2   = (float*)(smemc + SM_BC2);
    float* sBa2   = (float*)(smemc + SM_BA2);
    float* sW3    = (float*)(smemc + SM_W3);
    float* sVC1   = (float*)(smemc + SM_VC1);
    float* sVA1   = (float*)(smemc + SM_VA1);
    float* sScore = (float*)(smemc + SM_SCORE);
    float* sAtt   = (float*)(smemc + SM_ATT);
    float* coup   = g_coup + (size_t)b * 8192;

    copy_unit(0, sb + SM_B0, tid);
    copy_unit(1, sb + SM_B1, tid);

    if (tid < K_N) sIdx[tid] = act_users[(size_t)b * K_N + tid];
    if (tid >= 64 && tid < 192) {
        int c = tid - 64;
        sBfus[c] = b_fus[c];
        sBc2[c]  = b_c2[c];
        sBa2[c]  = b_a2[c];
        sW3[c]   = w_a3[c];
        sVC1[c]  = g_vec[(size_t)b * 128 + c];
        sVA1[c]  = g_vec[(size_t)Btot * 128 + (size_t)b * 128 + c];
    }
    // zero pad rows (50-63)
    for (int idx = tid; idx < 14 * 16; idx += 256) {
        int r = 50 + (idx >> 4);
        int c = idx & 15;
        int off = tile_off(r, c);
        *(uint4*)(smemc + SM_AHI + off) = make_uint4(0, 0, 0, 0);
        *(uint4*)(smemc + SM_ALO + off) = make_uint4(0, 0, 0, 0);
    }
    __syncthreads();                       // sIdx visible
    gatherA(emb_table, sIdx, smemc, tid);

    float acc[8][4];
#pragma unroll
    for (int t = 0; t < 8; ++t) {
        acc[t][0] = 0.f; acc[t][1] = 0.f; acc[t][2] = 0.f; acc[t][3] = 0.f;
    }

    WAITG(1); __syncthreads();             // A(emb) + unit0 ready
    sweep(acc, sb + SM_AHI, sb + SM_ALO, sb + SM_B0, wg, wr, l);
    __syncthreads();                       // B0 free
    copy_unit(2, sb + SM_B0, tid);
    gatherA(prof_table, sIdx, smemc, tid); // rewrite A (pads stay zero)
    WAITG(1); __syncthreads();             // A(prof) + unit1 ready
    sweep(acc, sb + SM_AHI, sb + SM_ALO, sb + SM_B1, wg, wr, l);
    __syncthreads();                       // B1 free
    copy_unit(3, sb + SM_B1, tid);
    epilogueA(acc, smemc, sBfus, nullptr, wg, wr, l);       // L1 -> fused
    WAITG(1); __syncthreads();
    sweep(acc, sb + SM_AHI, sb + SM_ALO, sb + SM_B0, wg, wr, l);   // L2
    __syncthreads();
    copy_unit(4, sb + SM_B0, tid);
    epilogueA(acc, smemc, sVC1, nullptr, wg, wr, l);        // L2 -> c1
    WAITG(1); __syncthreads();
    sweep(acc, sb + SM_AHI, sb + SM_ALO, sb + SM_B1, wg, wr, l);   // L3
    __syncthreads();
    copy_unit(5, sb + SM_B1, tid);
    epilogueA(acc, smemc, sBc2, coup, wg, wr, l);           // L3 -> coup (+gmem)
    WAITG(1); __syncthreads();
    sweep(acc, sb + SM_AHI, sb + SM_ALO, sb + SM_B0, wg, wr, l);   // L4
    __syncthreads();
    epilogueA(acc, smemc, sVA1, nullptr, wg, wr, l);        // L4 -> h
    WAITG(0); __syncthreads();
    sweep(acc, sb + SM_AHI, sb + SM_ALO, sb + SM_B1, wg, wr, l);   // L5
    epilogueScore(acc, sBa2, sW3, sScore, wg, wr, l);
    __syncthreads();

    // softmax over 50 scores (warp 0); halves summed here, +b3
    if (w == 0) {
        float b3 = b_a3[0];
        float v1 = (l < K_N)      ? sScore[l] + sScore[64 + l] + b3           : -1e30f;
        float v2 = (l + 32 < K_N) ? sScore[l + 32] + sScore[64 + l + 32] + b3 : -1e30f;
        float m = fmaxf(v1, v2);
#pragma unroll
        for (int o = 16; o; o >>= 1)
            m = fmaxf(m, __shfl_xor_sync(0xffffffffu, m, o));
        float e1 = (l < K_N)      ? expf(v1 - m) : 0.f;
        float e2 = (l + 32 < K_N) ? expf(v2 - m) : 0.f;
        float sum = e1 + e2;
#pragma unroll
        for (int o = 16; o; o >>= 1)
            sum += __shfl_xor_sync(0xffffffffu, sum, o);
        float inv = 1.f / sum;
        if (l < K_N)      sAtt[l]      = e1 * inv;
        if (l + 32 < K_N) sAtt[l + 32] = e2 * inv;
    }
    __syncthreads();

    // combined[col] = sum_k att[k] * coup[k][col]
    if (tid < 128) {
        float a = 0.f;
#pragma unroll 2
        for (int k = 0; k < K_N; ++k)
            a = fmaf(sAtt[k], coup[(size_t)k * 128 + tid], a);
        out_combined[(size_t)b * 128 + tid] = a;
    } else if (tid < 128 + K_N) {
        int k = tid - 128;
        out_att[(size_t)b * K_N + k] = sAtt[k];
    }
}

// ---------------- host launcher ----------------
extern "C" void kernel_launch(void* const* d_in, const int* in_sizes, int n_in,
                              void* d_out, int out_size) {
    const float* u_embs = (const float*)d_in[1];
    const float* i_embs = (const float*)d_in[3];
    const float* act    = (const float*)d_in[4];   // int32 data
    const float* table  = (const float*)d_in[5];
    const float* prof   = (const float*)d_in[6];
    const float* w_fus  = (const float*)d_in[7];
    const float* b_fus  = (const float*)d_in[8];
    const float* w_c1   = (const float*)d_in[9];
    const float* b_c1   = (const float*)d_in[10];
    const float* w_c2   = (const float*)d_in[11];
    const float* b_c2   = (const float*)d_in[12];
    const float* w_a1   = (const float*)d_in[13];
    const float* b_a1   = (const float*)d_in[14];
    const float* w_a2   = (const float*)d_in[15];
    const float* b_a2   = (const float*)d_in[16];
    const float* w_a3   = (const float*)d_in[17];
    const float* b_a3   = (const float*)d_in[18];

    int B = in_sizes[0];   // 4096

    float* out_combined = (float*)d_out;
    float* out_att      = out_combined + (size_t)B * 128;

    prep_weights<<<48, 256>>>(w_fus, w_c1, w_c2, w_a1, w_a2);
    prep_vecs<<<dim3(B, 2), 128>>>(i_embs, u_embs, w_c1, b_c1, w_a1, b_a1, B);

    cudaFuncSetAttribute(influence_main,
                         cudaFuncAttributeMaxDynamicSharedMemorySize, SM_TOTAL);
    influence_main<<<B, 256, SM_TOTAL>>>(
        act, table, prof,
        b_fus, b_c2, b_a2, w_a3, b_a3, B,
        out_combined, out_att);
}

// round 10
// speedup vs baseline: 3.0372x; 1.1708x over previous
#include <cuda_runtime.h>
#include <cuda_fp16.h>
#include <cstdint>

// InfluenceProp R10: single-term fp16 HMMA (A and B both fp16-rn, fp32 acc).
// Calibrated error: B-rounding alone measured 1.89e-4; A-rounding adds ~sqrt2x
// -> ~3e-4, under the 1e-3 gate. Halves MMA count vs R9; smem 86KB, 2 CTAs/SM.

#define K_N 50

// ---------------- gmem scratch ----------------
__device__ __align__(1024) __half g_wb[6 * 16384];   // 6 units x 128x128 fp16
__device__ float g_vec[2ull * 4096 * 128];           // folded biases [which][b][128]
__device__ float g_coup[4096ull * 8192];             // per-CTA coup fp32 [64][128]

// ---------------- smem byte offsets ----------------
#define SM_A     0          // 64x128 fp16 swizzled (16KB)
#define SM_B0    16384      // 128x128 fp16 (32KB)
#define SM_B1    49152
#define SM_IDX   81920
#define SM_BFUS  82176
#define SM_BC2   82688
#define SM_BA2   83200
#define SM_W3    83712
#define SM_VC1   84224
#define SM_VA1   84736
#define SM_SCORE 85248      // [2][64] partial scores
#define SM_ATT   85760
#define SM_TOTAL 86016

// tile layout: row r, 256 B/row; 16B chunk c stored at (c ^ (r&7))
__device__ __host__ __forceinline__ int tile_off(int r, int c) {
    return r * 256 + ((c ^ (r & 7)) << 4);
}

__device__ __forceinline__ uint32_t smem_u32(const void* p) {
    uint32_t a;
    asm("{ .reg .u64 t; cvta.to.shared.u64 t, %1; cvt.u32.u64 %0, t; }" : "=r"(a) : "l"(p));
    return a;
}

#define LDSM4(r0, r1, r2, r3, addr) \
    asm volatile("ldmatrix.sync.aligned.m8n8.x4.shared.b16 {%0,%1,%2,%3}, [%4];" \
                 : "=r"(r0), "=r"(r1), "=r"(r2), "=r"(r3) : "r"(addr))
#define MMA(ac, a0, a1, a2, a3, b0, b1) \
    asm volatile("mma.sync.aligned.m16n8k16.row.col.f32.f16.f16.f32 " \
                 "{%0,%1,%2,%3},{%4,%5,%6,%7},{%8,%9},{%0,%1,%2,%3};" \
                 : "+f"((ac)[0]), "+f"((ac)[1]), "+f"((ac)[2]), "+f"((ac)[3]) \
                 : "r"(a0), "r"(a1), "r"(a2), "r"(a3), "r"(b0), "r"(b1))

__device__ __forceinline__ uint32_t pkf2(float a, float b) {
    __half2 t = __floats2half2_rn(a, b);
    uint32_t u; __builtin_memcpy(&u, &t, 4);
    return u;
}

// ---------------- prepass 1: weight fp16 + transpose + swizzle ----------------
__global__ void prep_weights(
    const float* __restrict__ w_fus, const float* __restrict__ w_c1,
    const float* __restrict__ w_c2,  const float* __restrict__ w_a1,
    const float* __restrict__ w_a2)
{
    int u = blockIdx.x >> 3;
    int part = blockIdx.x & 7;
    const float* base; int koff = 0;
    if      (u == 0) { base = w_fus; }
    else if (u == 1) { base = w_fus; koff = 128; }
    else if (u == 2) { base = w_c1; }
    else if (u == 3) { base = w_c2; }
    else if (u == 4) { base = w_a1; }
    else             { base = w_a2; }

    int e0 = part * 2048;
    for (int i = threadIdx.x; i < 2048; i += blockDim.x) {
        int e = e0 + i;
        int n = e >> 7, k = e & 127;
        float v = base[(size_t)(k + koff) * 128 + n];
        int elem = (n * 256 + (((k >> 3) ^ (n & 7)) << 4) + (k & 7) * 2) >> 1;
        g_wb[(size_t)u * 16384 + elem] = __float2half_rn(v);
    }
}

// ---------------- prepass 2: folded per-sample bias vectors ----------------
__global__ void prep_vecs(
    const float* __restrict__ i_embs, const float* __restrict__ u_embs,
    const float* __restrict__ w_c1,   const float* __restrict__ b_c1,
    const float* __restrict__ w_a1,   const float* __restrict__ b_a1,
    int Btot)
{
    int b = blockIdx.x;
    int which = blockIdx.y;
    int col = threadIdx.x;
    const float* emb = which ? u_embs : i_embs;
    const float* W   = (which ? w_a1 : w_c1) + (size_t)128 * 128;
    const float* bb  = which ? b_a1 : b_c1;
    float acc = bb[col];
#pragma unroll 4
    for (int i = 0; i < 128; ++i)
        acc = fmaf(emb[(size_t)b * 128 + i], W[(size_t)i * 128 + col], acc);
    g_vec[(size_t)which * Btot * 128 + (size_t)b * 128 + col] = acc;
}

// ---------------- main kernel pieces ----------------
__device__ __forceinline__ void copy_unit(int u, uint32_t dstAddr, int tid) {
    const char* src = (const char*)g_wb + (size_t)u * 32768;
#pragma unroll
    for (int t = 0; t < 8; ++t) {
        int i = tid + t * 256;             // 0..2047 16B lines
        asm volatile("cp.async.cg.shared.global [%0], [%1], 16;"
                     :: "r"(dstAddr + i * 16), "l"(src + (size_t)i * 16));
    }
    asm volatile("cp.async.commit_group;" ::: "memory");
}

// single-term sweep over K=128: warp (wg, wr) computes rows [16wr,16wr+16) x
// cols [64wg, 64wg+64). acc[8][4].
__device__ __forceinline__ void sweep(
    float (&acc)[8][4],
    uint32_t aT, uint32_t bB,
    int wg, int wr, int l)
{
    const int rA = 16 * wr + (l & 15);
    const uint32_t aRowOff = (uint32_t)rA * 256;
    const int axor = rA & 7;
    const int khA = l >> 4;
    const uint32_t bLane = (uint32_t)(((l >> 4) & 1) * 2048 + (l & 7) * 256);
    const int bKh  = (l >> 3) & 1;
    const int bxor = l & 7;
    const uint32_t bGrp = (uint32_t)wg * 16384;   // tiles 8wg..8wg+7

#pragma unroll 1
    for (int ks = 0; ks < 8; ++ks) {
        uint32_t aoff = aRowOff + (uint32_t)(((2 * ks + khA) ^ axor) << 4);
        uint32_t a0, a1, a2, a3;
        LDSM4(a0, a1, a2, a3, aT + aoff);

        uint32_t bko = bGrp + bLane + (uint32_t)(((2 * ks + bKh) ^ bxor) << 4);

        uint32_t bh[8][2];
#pragma unroll
        for (int p = 0; p < 4; ++p)
            LDSM4(bh[2 * p][0], bh[2 * p][1], bh[2 * p + 1][0], bh[2 * p + 1][1],
                  bB + (uint32_t)p * 4096 + bko);

#pragma unroll
        for (int t = 0; t < 8; ++t)
            MMA(acc[t], a0, a1, a2, a3, bh[t][0], bh[t][1]);
    }
}

// gather table rows -> fp16 -> swizzled A tile (rows 0..49)
__device__ __forceinline__ void gatherA(
    const float* __restrict__ tbl, const int* sIdx, char* smemc, int tid)
{
    for (int idx = tid; idx < 800; idx += 256) {
        int r = idx >> 4;                 // 0..49
        int c = idx & 15;
        int u = sIdx[r];
        const float4* src = (const float4*)(tbl + (size_t)u * 128 + c * 8);
        float4 v0 = src[0], v1 = src[1];
        uint4 hv = make_uint4(pkf2(v0.x, v0.y), pkf2(v0.z, v0.w),
                              pkf2(v1.x, v1.y), pkf2(v1.z, v1.w));
        *(uint4*)(smemc + SM_A + tile_off(r, c)) = hv;
    }
}

// bias + relu -> fp16 into A tile chunks [8wg,8wg+8) (opt: coup); resets acc
__device__ __forceinline__ void epilogueA(
    float (&acc)[8][4], char* smemc, const float* bias,
    float* coupBase, int wg, int wr, int l)
{
    int q  = 16 * wr + (l >> 2);
    int p2 = (l & 3) * 2;
    int r0 = q, r1 = q + 8;
#pragma unroll
    for (int t = 0; t < 8; ++t) {
        int n = 64 * wg + 8 * t + p2;
        float y00 = fmaxf(acc[t][0] + bias[n],     0.f);
        float y01 = fmaxf(acc[t][1] + bias[n + 1], 0.f);
        float y10 = fmaxf(acc[t][2] + bias[n],     0.f);
        float y11 = fmaxf(acc[t][3] + bias[n + 1], 0.f);
        acc[t][0] = 0.f; acc[t][1] = 0.f; acc[t][2] = 0.f; acc[t][3] = 0.f;
        *(uint32_t*)(smemc + SM_A + tile_off(r0, 8 * wg + t) + p2 * 2) = pkf2(y00, y01);
        *(uint32_t*)(smemc + SM_A + tile_off(r1, 8 * wg + t) + p2 * 2) = pkf2(y10, y11);
        if (coupBase) {
            *(float2*)(coupBase + (size_t)r0 * 128 + n) = make_float2(y00, y01);
            *(float2*)(coupBase + (size_t)r1 * 128 + n) = make_float2(y10, y11);
        }
    }
}

// last layer: bias+relu, partial dot with w3 over this warp's n-half
__device__ __forceinline__ void epilogueScore(
    float (&acc)[8][4], const float* ba2, const float* w3,
    float* sScore, int wg, int wr, int l)
{
    int q  = 16 * wr + (l >> 2);
    int p2 = (l & 3) * 2;
    float p0 = 0.f, p1 = 0.f;
#pragma unroll
    for (int t = 0; t < 8; ++t) {
        int n = 64 * wg + 8 * t + p2;
        p0 = fmaf(fmaxf(acc[t][0] + ba2[n],     0.f), w3[n],     p0);
        p0 = fmaf(fmaxf(acc[t][1] + ba2[n + 1], 0.f), w3[n + 1], p0);
        p1 = fmaf(fmaxf(acc[t][2] + ba2[n],     0.f), w3[n],     p1);
        p1 = fmaf(fmaxf(acc[t][3] + ba2[n + 1], 0.f), w3[n + 1], p1);
    }
    p0 += __shfl_xor_sync(0xffffffffu, p0, 1);
    p0 += __shfl_xor_sync(0xffffffffu, p0, 2);
    p1 += __shfl_xor_sync(0xffffffffu, p1, 1);
    p1 += __shfl_xor_sync(0xffffffffu, p1, 2);
    if ((l & 3) == 0) {
        sScore[wg * 64 + q]     = p0;
        sScore[wg * 64 + q + 8] = p1;
    }
}

#define WAITG(n) asm volatile("cp.async.wait_group %0;" :: "n"(n) : "memory")

__global__ __launch_bounds__(256, 2)
void influence_main(
    const float* __restrict__ act_users_f,
    const float* __restrict__ emb_table, const float* __restrict__ prof_table,
    const float* __restrict__ b_fus, const float* __restrict__ b_c2,
    const float* __restrict__ b_a2,  const float* __restrict__ w_a3,
    const float* __restrict__ b_a3,
    int Btot,
    float* __restrict__ out_combined, float* __restrict__ out_att)
{
    extern __shared__ char smemc[];
    const int tid = threadIdx.x;
    const int w = tid >> 5, l = tid & 31;
    const int wg = w >> 2, wr = w & 3;
    const int b = blockIdx.x;
    const int* act_users = (const int*)act_users_f;
    uint32_t sb = smem_u32(smemc);

    int* sIdx     = (int*)(smemc + SM_IDX);
    float* sBfus  = (float*)(smemc + SM_BFUS);
    float* sBc2   = (float*)(smemc + SM_BC2);
    float* sBa2   = (float*)(smemc + SM_BA2);
    float* sW3    = (float*)(smemc + SM_W3);
    float* sVC1   = (float*)(smemc + SM_VC1);
    float* sVA1   = (float*)(smemc + SM_VA1);
    float* sScore = (float*)(smemc + SM_SCORE);
    float* sAtt   = (float*)(smemc + SM_ATT);
    float* coup   = g_coup + (size_t)b * 8192;

    copy_unit(0, sb + SM_B0, tid);
    copy_unit(1, sb + SM_B1, tid);

    if (tid < K_N) sIdx[tid] = act_users[(size_t)b * K_N + tid];
    if (tid >= 64 && tid < 192) {
        int c = tid - 64;
        sBfus[c] = b_fus[c];
        sBc2[c]  = b_c2[c];
        sBa2[c]  = b_a2[c];
        sW3[c]   = w_a3[c];
        sVC1[c]  = g_vec[(size_t)b * 128 + c];
        sVA1[c]  = g_vec[(size_t)Btot * 128 + (size_t)b * 128 + c];
    }
    // zero pad rows (50-63)
    for (int idx = tid; idx < 14 * 16; idx += 256) {
        int r = 50 + (idx >> 4);
        int c = idx & 15;
        *(uint4*)(smemc + SM_A + tile_off(r, c)) = make_uint4(0, 0, 0, 0);
    }
    __syncthreads();                       // sIdx visible
    gatherA(emb_table, sIdx, smemc, tid);

    float acc[8][4];
#pragma unroll
    for (int t = 0; t < 8; ++t) {
        acc[t][0] = 0.f; acc[t][1] = 0.f; acc[t][2] = 0.f; acc[t][3] = 0.f;
    }

    WAITG(1); __syncthreads();             // A(emb) + unit0 ready
    sweep(acc, sb + SM_A, sb + SM_B0, wg, wr, l);
    __syncthreads();                       // B0 free
    copy_unit(2, sb + SM_B0, tid);
    gatherA(prof_table, sIdx, smemc, tid); // rewrite A (pads stay zero)
    WAITG(1); __syncthreads();             // A(prof) + unit1 ready
    sweep(acc, sb + SM_A, sb + SM_B1, wg, wr, l);
    __syncthreads();                       // B1 free
    copy_unit(3, sb + SM_B1, tid);
    epilogueA(acc, smemc, sBfus, nullptr, wg, wr, l);       // L1 -> fused
    WAITG(1); __syncthreads();
    sweep(acc, sb + SM_A, sb + SM_B0, wg, wr, l);           // L2
    __syncthreads();
    copy_unit(4, sb + SM_B0, tid);
    epilogueA(acc, smemc, sVC1, nullptr, wg, wr, l);        // L2 -> c1
    WAITG(1); __syncthreads();
    sweep(acc, sb + SM_A, sb + SM_B1, wg, wr, l);           // L3
    __syncthreads();
    copy_unit(5, sb + SM_B1, tid);
    epilogueA(acc, smemc, sBc2, coup, wg, wr, l);           // L3 -> coup (+gmem)
    WAITG(1); __syncthreads();
    sweep(acc, sb + SM_A, sb + SM_B0, wg, wr, l);           // L4
    __syncthreads();
    epilogueA(acc, smemc, sVA1, nullptr, wg, wr, l);        // L4 -> h
    WAITG(0); __syncthreads();
    sweep(acc, sb + SM_A, sb + SM_B1, wg, wr, l);           // L5
    epilogueScore(acc, sBa2, sW3, sScore, wg, wr, l);
    __syncthreads();

    // softmax over 50 scores (warp 0); halves summed here, +b3
    if (w == 0) {
        float b3 = b_a3[0];
        float v1 = (l < K_N)      ? sScore[l] + sScore[64 + l] + b3           : -1e30f;
        float v2 = (l + 32 < K_N) ? sScore[l + 32] + sScore[64 + l + 32] + b3 : -1e30f;
        float m = fmaxf(v1, v2);
#pragma unroll
        for (int o = 16; o; o >>= 1)
            m = fmaxf(m, __shfl_xor_sync(0xffffffffu, m, o));
        float e1 = (l < K_N)      ? expf(v1 - m) : 0.f;
        float e2 = (l + 32 < K_N) ? expf(v2 - m) : 0.f;
        float sum = e1 + e2;
#pragma unroll
        for (int o = 16; o; o >>= 1)
            sum += __shfl_xor_sync(0xffffffffu, sum, o);
        float inv = 1.f / sum;
        if (l < K_N)      sAtt[l]      = e1 * inv;
        if (l + 32 < K_N) sAtt[l + 32] = e2 * inv;
    }
    __syncthreads();

    // combined[col] = sum_k att[k] * coup[k][col]
    if (tid < 128) {
        float a = 0.f;
#pragma unroll 2
        for (int k = 0; k < K_N; ++k)
            a = fmaf(sAtt[k], coup[(size_t)k * 128 + tid], a);
        out_combined[(size_t)b * 128 + tid] = a;
    } else if (tid < 128 + K_N) {
        int k = tid - 128;
        out_att[(size_t)b * K_N + k] = sAtt[k];
    }
}

// ---------------- host launcher ----------------
extern "C" void kernel_launch(void* const* d_in, const int* in_sizes, int n_in,
                              void* d_out, int out_size) {
    const float* u_embs = (const float*)d_in[1];
    const float* i_embs = (const float*)d_in[3];
    const float* act    = (const float*)d_in[4];   // int32 data
    const float* table  = (const float*)d_in[5];
    const float* prof   = (const float*)d_in[6];
    const float* w_fus  = (const float*)d_in[7];
    const float* b_fus  = (const float*)d_in[8];
    const float* w_c1   = (const float*)d_in[9];
    const float* b_c1   = (const float*)d_in[10];
    const float* w_c2   = (const float*)d_in[11];
    const float* b_c2   = (const float*)d_in[12];
    const float* w_a1   = (const float*)d_in[13];
    const float* b_a1   = (const float*)d_in[14];
    const float* w_a2   = (const float*)d_in[15];
    const float* b_a2   = (const float*)d_in[16];
    const float* w_a3   = (const float*)d_in[17];
    const float* b_a3   = (const float*)d_in[18];

    int B = in_sizes[0];   // 4096

    float* out_combined = (float*)d_out;
    float* out_att      = out_combined + (size_t)B * 128;

    prep_weights<<<48, 256>>>(w_fus, w_c1, w_c2, w_a1, w_a2);
    prep_vecs<<<dim3(B, 2), 128>>>(i_embs, u_embs, w_c1, b_c1, w_a1, b_a1, B);

    cudaFuncSetAttribute(influence_main,
                         cudaFuncAttributeMaxDynamicSharedMemorySize, SM_TOTAL);
    influence_main<<<B, 256, SM_TOTAL>>>(
        act, table, prof,
        b_fus, b_c2, b_a2, w_a3, b_a3, B,
        out_combined, out_att);
}

// round 11
// speedup vs baseline: 3.6642x; 1.2064x over previous
#include <cuda_runtime.h>
#include <cuda_fp16.h>
#include <cstdint>

// InfluenceProp R11: single-term fp16 HMMA, 2 samples/CTA (M=128) AND
// 2 CTAs/SM (smem ~102KB). Halves per-sample overhead (B copies, gathers,
// barriers) while keeping cross-CTA latency hiding. B fragments loaded in
// two 8-tile halves to stay under 128 regs for occupancy 2.

#define K_N 50

// ---------------- gmem scratch ----------------
__device__ __align__(1024) __half g_wb[6 * 16384];   // 6 units x 128x128 fp16
__device__ float g_vec[2ull * 4096 * 128];           // folded biases [which][b][128]
__device__ float g_coup[2048ull * 16384];            // per-CTA coup fp32 [128][128]

// ---------------- smem byte offsets ----------------
#define SM_A     0          // 128x128 fp16 swizzled (32KB)
#define SM_B0    32768      // 128x128 fp16 (32KB)
#define SM_B1    65536
#define SM_IDX   98304      // 128 ints
#define SM_BFUS  98816
#define SM_BC2   99328
#define SM_BA2   99840
#define SM_W3    100352
#define SM_VC1   100864     // [2][128]
#define SM_VA1   101888     // [2][128]
#define SM_SCORE 102912     // [128]
#define SM_ATT   103424     // [2][64]
#define SM_TOTAL 103936

// tile layout: row r, 256 B/row; 16B chunk c stored at (c ^ (r&7))
__device__ __host__ __forceinline__ int tile_off(int r, int c) {
    return r * 256 + ((c ^ (r & 7)) << 4);
}

__device__ __forceinline__ uint32_t smem_u32(const void* p) {
    uint32_t a;
    asm("{ .reg .u64 t; cvta.to.shared.u64 t, %1; cvt.u32.u64 %0, t; }" : "=r"(a) : "l"(p));
    return a;
}

#define LDSM4(r0, r1, r2, r3, addr) \
    asm volatile("ldmatrix.sync.aligned.m8n8.x4.shared.b16 {%0,%1,%2,%3}, [%4];" \
                 : "=r"(r0), "=r"(r1), "=r"(r2), "=r"(r3) : "r"(addr))
#define MMA(ac, a0, a1, a2, a3, b0, b1) \
    asm volatile("mma.sync.aligned.m16n8k16.row.col.f32.f16.f16.f32 " \
                 "{%0,%1,%2,%3},{%4,%5,%6,%7},{%8,%9},{%0,%1,%2,%3};" \
                 : "+f"((ac)[0]), "+f"((ac)[1]), "+f"((ac)[2]), "+f"((ac)[3]) \
                 : "r"(a0), "r"(a1), "r"(a2), "r"(a3), "r"(b0), "r"(b1))

__device__ __forceinline__ uint32_t pkf2(float a, float b) {
    __half2 t = __floats2half2_rn(a, b);
    uint32_t u; __builtin_memcpy(&u, &t, 4);
    return u;
}

// ---------------- prepass 1: weight fp16 + transpose + swizzle ----------------
__global__ void prep_weights(
    const float* __restrict__ w_fus, const float* __restrict__ w_c1,
    const float* __restrict__ w_c2,  const float* __restrict__ w_a1,
    const float* __restrict__ w_a2)
{
    int u = blockIdx.x >> 3;
    int part = blockIdx.x & 7;
    const float* base; int koff = 0;
    if      (u == 0) { base = w_fus; }
    else if (u == 1) { base = w_fus; koff = 128; }
    else if (u == 2) { base = w_c1; }
    else if (u == 3) { base = w_c2; }
    else if (u == 4) { base = w_a1; }
    else             { base = w_a2; }

    int e0 = part * 2048;
    for (int i = threadIdx.x; i < 2048; i += blockDim.x) {
        int e = e0 + i;
        int n = e >> 7, k = e & 127;
        float v = base[(size_t)(k + koff) * 128 + n];
        int elem = (n * 256 + (((k >> 3) ^ (n & 7)) << 4) + (k & 7) * 2) >> 1;
        g_wb[(size_t)u * 16384 + elem] = __float2half_rn(v);
    }
}

// ---------------- prepass 2: folded per-sample bias vectors ----------------
__global__ void prep_vecs(
    const float* __restrict__ i_embs, const float* __restrict__ u_embs,
    const float* __restrict__ w_c1,   const float* __restrict__ b_c1,
    const float* __restrict__ w_a1,   const float* __restrict__ b_a1,
    int Btot)
{
    int b = blockIdx.x;
    int which = blockIdx.y;
    int col = threadIdx.x;
    const float* emb = which ? u_embs : i_embs;
    const float* W   = (which ? w_a1 : w_c1) + (size_t)128 * 128;
    const float* bb  = which ? b_a1 : b_c1;
    float acc = bb[col];
#pragma unroll 4
    for (int i = 0; i < 128; ++i)
        acc = fmaf(emb[(size_t)b * 128 + i], W[(size_t)i * 128 + col], acc);
    g_vec[(size_t)which * Btot * 128 + (size_t)b * 128 + col] = acc;
}

// ---------------- main kernel pieces ----------------
__device__ __forceinline__ void copy_unit(int u, uint32_t dstAddr, int tid) {
    const char* src = (const char*)g_wb + (size_t)u * 32768;
#pragma unroll
    for (int t = 0; t < 8; ++t) {
        int i = tid + t * 256;             // 0..2047 16B lines
        asm volatile("cp.async.cg.shared.global [%0], [%1], 16;"
                     :: "r"(dstAddr + i * 16), "l"(src + (size_t)i * 16));
    }
    asm volatile("cp.async.commit_group;" ::: "memory");
}

// single-term sweep over K=128: warp w owns rows [16w,16w+16) x full N=128.
// acc[16][4]. B loaded in two 8-tile halves to limit live registers.
__device__ __forceinline__ void sweep(
    float (&acc)[16][4],
    uint32_t aT, uint32_t bB,
    int w, int l)
{
    const int rA = 16 * w + (l & 15);
    const uint32_t aRowOff = (uint32_t)rA * 256;
    const int axor = rA & 7;
    const int khA = l >> 4;
    const uint32_t bLane = (uint32_t)(((l >> 4) & 1) * 2048 + (l & 7) * 256);
    const int bKh  = (l >> 3) & 1;
    const int bxor = l & 7;

#pragma unroll 1
    for (int ks = 0; ks < 8; ++ks) {
        uint32_t aoff = aRowOff + (uint32_t)(((2 * ks + khA) ^ axor) << 4);
        uint32_t a0, a1, a2, a3;
        LDSM4(a0, a1, a2, a3, aT + aoff);

        uint32_t bko = bLane + (uint32_t)(((2 * ks + bKh) ^ bxor) << 4);

        uint32_t bh[8][2];
#pragma unroll
        for (int p = 0; p < 4; ++p)
            LDSM4(bh[2 * p][0], bh[2 * p][1], bh[2 * p + 1][0], bh[2 * p + 1][1],
                  bB + (uint32_t)p * 4096 + bko);
#pragma unroll
        for (int t = 0; t < 8; ++t)
            MMA(acc[t], a0, a1, a2, a3, bh[t][0], bh[t][1]);
#pragma unroll
        for (int p = 0; p < 4; ++p)
            LDSM4(bh[2 * p][0], bh[2 * p][1], bh[2 * p + 1][0], bh[2 * p + 1][1],
                  bB + (uint32_t)(p + 4) * 4096 + bko);
#pragma unroll
        for (int t = 0; t < 8; ++t)
            MMA(acc[t + 8], a0, a1, a2, a3, bh[t][0], bh[t][1]);
    }
}

// gather table rows -> fp16 -> swizzled A tile (rows s*64+k, k<50)
__device__ __forceinline__ void gatherA(
    const float* __restrict__ tbl, const int* sIdx, char* smemc, int tid)
{
    for (int idx = tid; idx < 1600; idx += 256) {
        int rowi = idx >> 4;                 // 0..99
        int s = (rowi >= 50) ? 1 : 0;
        int k = rowi - s * 50;
        int r = s * 64 + k;
        int c = idx & 15;
        int u = sIdx[s * 64 + k];
        const float4* src = (const float4*)(tbl + (size_t)u * 128 + c * 8);
        float4 v0 = src[0], v1 = src[1];
        uint4 hv = make_uint4(pkf2(v0.x, v0.y), pkf2(v0.z, v0.w),
                              pkf2(v1.x, v1.y), pkf2(v1.z, v1.w));
        *(uint4*)(smemc + SM_A + tile_off(r, c)) = hv;
    }
}

// bias + relu -> fp16 back into A tile (opt: fp32 coup to gmem); resets acc
__device__ __forceinline__ void epilogueA(
    float (&acc)[16][4], char* smemc,
    const float* bias0, const float* bias1,
    float* coupBase, int w, int l)
{
    int q  = 16 * w + (l >> 2);
    int p2 = (l & 3) * 2;
    const float* bA = (q < 64) ? bias0 : bias1;
    int r0 = q, r1 = q + 8;
#pragma unroll
    for (int t = 0; t < 16; ++t) {
        int n = 8 * t + p2;
        float y00 = fmaxf(acc[t][0] + bA[n],     0.f);
        float y01 = fmaxf(acc[t][1] + bA[n + 1], 0.f);
        float y10 = fmaxf(acc[t][2] + bA[n],     0.f);
        float y11 = fmaxf(acc[t][3] + bA[n + 1], 0.f);
        acc[t][0] = 0.f; acc[t][1] = 0.f; acc[t][2] = 0.f; acc[t][3] = 0.f;
        *(uint32_t*)(smemc + SM_A + tile_off(r0, t) + p2 * 2) = pkf2(y00, y01);
        *(uint32_t*)(smemc + SM_A + tile_off(r1, t) + p2 * 2) = pkf2(y10, y11);
        if (coupBase) {
            *(float2*)(coupBase + (size_t)r0 * 128 + n) = make_float2(y00, y01);
            *(float2*)(coupBase + (size_t)r1 * 128 + n) = make_float2(y10, y11);
        }
    }
}

// last layer: bias+relu, dot with w3 (full N per warp), quad reduce -> sScore
__device__ __forceinline__ void epilogueScore(
    float (&acc)[16][4], const float* ba2, const float* w3, float b3,
    float* sScore, int w, int l)
{
    int q  = 16 * w + (l >> 2);
    int p2 = (l & 3) * 2;
    float p0 = 0.f, p1 = 0.f;
#pragma unroll
    for (int t = 0; t < 16; ++t) {
        int n = 8 * t + p2;
        p0 = fmaf(fmaxf(acc[t][0] + ba2[n],     0.f), w3[n],     p0);
        p0 = fmaf(fmaxf(acc[t][1] + ba2[n + 1], 0.f), w3[n + 1], p0);
        p1 = fmaf(fmaxf(acc[t][2] + ba2[n],     0.f), w3[n],     p1);
        p1 = fmaf(fmaxf(acc[t][3] + ba2[n + 1], 0.f), w3[n + 1], p1);
    }
    p0 += __shfl_xor_sync(0xffffffffu, p0, 1);
    p0 += __shfl_xor_sync(0xffffffffu, p0, 2);
    p1 += __shfl_xor_sync(0xffffffffu, p1, 1);
    p1 += __shfl_xor_sync(0xffffffffu, p1, 2);
    if ((l & 3) == 0) {
        sScore[q]     = p0 + b3;
        sScore[q + 8] = p1 + b3;
    }
}

#define WAITG(n) asm volatile("cp.async.wait_group %0;" :: "n"(n) : "memory")

__global__ __launch_bounds__(256, 2)
void influence_main(
    const float* __restrict__ act_users_f,
    const float* __restrict__ emb_table, const float* __restrict__ prof_table,
    const float* __restrict__ b_fus, const float* __restrict__ b_c2,
    const float* __restrict__ b_a2,  const float* __restrict__ w_a3,
    const float* __restrict__ b_a3,
    int Btot,
    float* __restrict__ out_combined, float* __restrict__ out_att)
{
    extern __shared__ char smemc[];
    const int tid = threadIdx.x;
    const int w = tid >> 5, l = tid & 31;
    const int b0 = blockIdx.x * 2;
    const int* act_users = (const int*)act_users_f;
    uint32_t sb = smem_u32(smemc);

    int* sIdx     = (int*)(smemc + SM_IDX);
    float* sBfus  = (float*)(smemc + SM_BFUS);
    float* sBc2   = (float*)(smemc + SM_BC2);
    float* sBa2   = (float*)(smemc + SM_BA2);
    float* sW3    = (float*)(smemc + SM_W3);
    float* sVC1   = (float*)(smemc + SM_VC1);
    float* sVA1   = (float*)(smemc + SM_VA1);
    float* sScore = (float*)(smemc + SM_SCORE);
    float* sAtt   = (float*)(smemc + SM_ATT);
    float* coup   = g_coup + (size_t)blockIdx.x * 16384;

    copy_unit(0, sb + SM_B0, tid);
    copy_unit(1, sb + SM_B1, tid);

    if (tid < 100) {
        int s = tid / 50, k = tid - s * 50;
        sIdx[s * 64 + k] = act_users[(size_t)(b0 + s) * K_N + k];
    }
    if (tid < 128) {
        sBfus[tid] = b_fus[tid];
        sBc2[tid]  = b_c2[tid];
        sBa2[tid]  = b_a2[tid];
        sW3[tid]   = w_a3[tid];
    }
    if (tid >= 128 && tid < 256) {
        int c = tid - 128;
        sVC1[c]       = g_vec[(size_t)(b0 + 0) * 128 + c];
        sVC1[128 + c] = g_vec[(size_t)(b0 + 1) * 128 + c];
        sVA1[c]       = g_vec[(size_t)Btot * 128 + (size_t)(b0 + 0) * 128 + c];
        sVA1[128 + c] = g_vec[(size_t)Btot * 128 + (size_t)(b0 + 1) * 128 + c];
    }
    // zero pad rows (50-63, 114-127)
    for (int idx = tid; idx < 28 * 16; idx += 256) {
        int pr = idx >> 4;
        int r = (pr < 14) ? (50 + pr) : (100 + pr);
        int c = idx & 15;
        *(uint4*)(smemc + SM_A + tile_off(r, c)) = make_uint4(0, 0, 0, 0);
    }
    __syncthreads();                       // sIdx visible
    gatherA(emb_table, sIdx, smemc, tid);

    float acc[16][4];
#pragma unroll
    for (int t = 0; t < 16; ++t) {
        acc[t][0] = 0.f; acc[t][1] = 0.f; acc[t][2] = 0.f; acc[t][3] = 0.f;
    }

    WAITG(1); __syncthreads();             // A(emb) + unit0 ready
    sweep(acc, sb + SM_A, sb + SM_B0, w, l);
    __syncthreads();                       // B0 free
    copy_unit(2, sb + SM_B0, tid);
    gatherA(prof_table, sIdx, smemc, tid); // rewrite A (pads stay zero)
    WAITG(1); __syncthreads();             // A(prof) + unit1 ready
    sweep(acc, sb + SM_A, sb + SM_B1, w, l);
    __syncthreads();                       // B1 free
    copy_unit(3, sb + SM_B1, tid);
    epilogueA(acc, smemc, sBfus, sBfus, nullptr, w, l);      // L1 -> fused
    WAITG(1); __syncthreads();
    sweep(acc, sb + SM_A, sb + SM_B0, w, l);                 // L2
    __syncthreads();
    copy_unit(4, sb + SM_B0, tid);
    epilogueA(acc, smemc, sVC1, sVC1 + 128, nullptr, w, l);  // L2 -> c1
    WAITG(1); __syncthreads();
    sweep(acc, sb + SM_A, sb + SM_B1, w, l);                 // L3
    __syncthreads();
    copy_unit(5, sb + SM_B1, tid);
    epilogueA(acc, smemc, sBc2, sBc2, coup, w, l);           // L3 -> coup (+gmem)
    WAITG(1); __syncthreads();
    sweep(acc, sb + SM_A, sb + SM_B0, w, l);                 // L4
    __syncthreads();
    epilogueA(acc, smemc, sVA1, sVA1 + 128, nullptr, w, l);  // L4 -> h
    WAITG(0); __syncthreads();
    sweep(acc, sb + SM_A, sb + SM_B1, w, l);                 // L5
    epilogueScore(acc, sBa2, sW3, b_a3[0], sScore, w, l);
    __syncthreads();

    // softmax per sample (warp 0 -> s0, warp 2 -> s1)
    if (w == 0 || w == 2) {
        int s = w >> 1;
        int base = s * 64;
        float v1 = (l < K_N)      ? sScore[base + l]      : -1e30f;
        float v2 = (l + 32 < K_N) ? sScore[base + l + 32] : -1e30f;
        float m = fmaxf(v1, v2);
#pragma unroll
        for (int o = 16; o; o >>= 1)
            m = fmaxf(m, __shfl_xor_sync(0xffffffffu, m, o));
        float e1 = (l < K_N)      ? expf(v1 - m) : 0.f;
        float e2 = (l + 32 < K_N) ? expf(v2 - m) : 0.f;
        float sum = e1 + e2;
#pragma unroll
        for (int o = 16; o; o >>= 1)
            sum += __shfl_xor_sync(0xffffffffu, sum, o);
        float inv = 1.f / sum;
        if (l < K_N)      sAtt[base + l]      = e1 * inv;
        if (l + 32 < K_N) sAtt[base + l + 32] = e2 * inv;
    }
    __syncthreads();

    // combined[s][col] = sum_k att[s][k] * coup[s*64+k][col]
    {
        int s = tid >> 7, col = tid & 127;
        float a = 0.f;
#pragma unroll 2
        for (int k = 0; k < K_N; ++k)
            a = fmaf(sAtt[s * 64 + k], coup[(size_t)(s * 64 + k) * 128 + col], a);
        out_combined[(size_t)(b0 + s) * 128 + col] = a;
    }
    if (tid < 2 * K_N) {
        int s = tid / K_N, k = tid - s * K_N;
        out_att[(size_t)(b0 + s) * K_N + k] = sAtt[s * 64 + k];
    }
}

// ---------------- host launcher ----------------
extern "C" void kernel_launch(void* const* d_in, const int* in_sizes, int n_in,
                              void* d_out, int out_size) {
    const float* u_embs = (const float*)d_in[1];
    const float* i_embs = (const float*)d_in[3];
    const float* act    = (const float*)d_in[4];   // int32 data
    const float* table  = (const float*)d_in[5];
    const float* prof   = (const float*)d_in[6];
    const float* w_fus  = (const float*)d_in[7];
    const float* b_fus  = (const float*)d_in[8];
    const float* w_c1   = (const float*)d_in[9];
    const float* b_c1   = (const float*)d_in[10];
    const float* w_c2   = (const float*)d_in[11];
    const float* b_c2   = (const float*)d_in[12];
    const float* w_a1   = (const float*)d_in[13];
    const float* b_a1   = (const float*)d_in[14];
    const float* w_a2   = (const float*)d_in[15];
    const float* b_a2   = (const float*)d_in[16];
    const float* w_a3   = (const float*)d_in[17];
    const float* b_a3   = (const float*)d_in[18];

    int B = in_sizes[0];   // 4096

    float* out_combined = (float*)d_out;
    float* out_att      = out_combined + (size_t)B * 128;

    prep_weights<<<48, 256>>>(w_fus, w_c1, w_c2, w_a1, w_a2);
    prep_vecs<<<dim3(B, 2), 128>>>(i_embs, u_embs, w_c1, b_c1, w_a1, b_a1, B);

    cudaFuncSetAttribute(influence_main,
                         cudaFuncAttributeMaxDynamicSharedMemorySize, SM_TOTAL);
    influence_main<<<B / 2, 256, SM_TOTAL>>>(
        act, table, prof,
        b_fus, b_c2, b_a2, w_a3, b_a3, B,
        out_combined, out_att);
}

// round 12
// speedup vs baseline: 3.7248x; 1.0165x over previous
#include <cuda_runtime.h>
#include <cuda_fp16.h>
#include <cstdint>

// InfluenceProp R12: single-term fp16 HMMA, 5 samples/CTA (M=256, rows packed
// at 50s+k, only 6/256 pad rows), 512 threads / 16 warps (SMSP-balanced),
// 1 CTA/SM (smem ~138KB). prep_vecs rewritten with 16-sample W reuse
// (L2 traffic 512MB -> 32MB). Pad-row zeroing dropped (pads only feed pad
// outputs). Per-sample math order identical to R11 -> same rel_err.

#define K_N 50
#define NS 5
#define NTHREADS 512

// ---------------- gmem scratch ----------------
__device__ __align__(1024) __half g_wb[6 * 16384];   // 6 units x 128x128 fp16
__device__ float g_vec[2ull * 4096 * 128];           // folded biases [which][b][128]
__device__ float g_coup[832ull * 32768];             // per-CTA coup fp32 [256][128]

// ---------------- smem byte offsets ----------------
#define SM_A     0          // 256x128 fp16 swizzled (64KB)
#define SM_B0    65536      // 128x128 fp16 (32KB)
#define SM_B1    98304
#define SM_IDX   131072     // 256 ints
#define SM_BFUS  132096
#define SM_BC2   132608
#define SM_BA2   133120
#define SM_W3    133632
#define SM_VC1   134144     // [5][128] f
#define SM_VA1   136704     // [5][128] f
#define SM_SCORE 139264     // [256] f
#define SM_ATT   140288     // [5][64] f
#define SM_TOTAL 141568

// tile layout: row r, 256 B/row; 16B chunk c stored at (c ^ (r&7))
__device__ __host__ __forceinline__ int tile_off(int r, int c) {
    return r * 256 + ((c ^ (r & 7)) << 4);
}

__device__ __forceinline__ uint32_t smem_u32(const void* p) {
    uint32_t a;
    asm("{ .reg .u64 t; cvta.to.shared.u64 t, %1; cvt.u32.u64 %0, t; }" : "=r"(a) : "l"(p));
    return a;
}

#define LDSM4(r0, r1, r2, r3, addr) \
    asm volatile("ldmatrix.sync.aligned.m8n8.x4.shared.b16 {%0,%1,%2,%3}, [%4];" \
                 : "=r"(r0), "=r"(r1), "=r"(r2), "=r"(r3) : "r"(addr))
#define MMA(ac, a0, a1, a2, a3, b0, b1) \
    asm volatile("mma.sync.aligned.m16n8k16.row.col.f32.f16.f16.f32 " \
                 "{%0,%1,%2,%3},{%4,%5,%6,%7},{%8,%9},{%0,%1,%2,%3};" \
                 : "+f"((ac)[0]), "+f"((ac)[1]), "+f"((ac)[2]), "+f"((ac)[3]) \
                 : "r"(a0), "r"(a1), "r"(a2), "r"(a3), "r"(b0), "r"(b1))

__device__ __forceinline__ uint32_t pkf2(float a, float b) {
    __half2 t = __floats2half2_rn(a, b);
    uint32_t u; __builtin_memcpy(&u, &t, 4);
    return u;
}

// ---------------- prepass 1: weight fp16 + transpose + swizzle ----------------
__global__ void prep_weights(
    const float* __restrict__ w_fus, const float* __restrict__ w_c1,
    const float* __restrict__ w_c2,  const float* __restrict__ w_a1,
    const float* __restrict__ w_a2)
{
    int u = blockIdx.x >> 3;
    int part = blockIdx.x & 7;
    const float* base; int koff = 0;
    if      (u == 0) { base = w_fus; }
    else if (u == 1) { base = w_fus; koff = 128; }
    else if (u == 2) { base = w_c1; }
    else if (u == 3) { base = w_c2; }
    else if (u == 4) { base = w_a1; }
    else             { base = w_a2; }

    int e0 = part * 2048;
    for (int i = threadIdx.x; i < 2048; i += blockDim.x) {
        int e = e0 + i;
        int n = e >> 7, k = e & 127;
        float v = base[(size_t)(k + koff) * 128 + n];
        int elem = (n * 256 + (((k >> 3) ^ (n & 7)) << 4) + (k & 7) * 2) >> 1;
        g_wb[(size_t)u * 16384 + elem] = __float2half_rn(v);
    }
}

// ---------------- prepass 2: folded bias vectors, 16 samples/block ----------------
__global__ void prep_vecs2(
    const float* __restrict__ i_embs, const float* __restrict__ u_embs,
    const float* __restrict__ w_c1,   const float* __restrict__ b_c1,
    const float* __restrict__ w_a1,   const float* __restrict__ b_a1,
    int Btot)
{
    __shared__ float sE[16 * 128];
    __shared__ float sW[32 * 128];
    int which = blockIdx.y;
    int bbase = blockIdx.x * 16;
    const float* emb = which ? u_embs : i_embs;
    const float* W   = (which ? w_a1 : w_c1) + (size_t)128 * 128;
    const float* bb  = which ? b_a1 : b_c1;
    int tid = threadIdx.x;

    for (int idx = tid; idx < 2048; idx += 256) {
        int s = idx >> 7, c = idx & 127;
        sE[idx] = (bbase + s < Btot) ? emb[(size_t)(bbase + s) * 128 + c] : 0.f;
    }
    int col = tid & 127;
    int sg  = tid >> 7;                 // samples sg*8 .. sg*8+7
    float acc[8];
#pragma unroll
    for (int j = 0; j < 8; ++j) acc[j] = bb[col];

    for (int kc = 0; kc < 4; ++kc) {
        __syncthreads();                // sE (kc=0) / prior sW reads done
        for (int idx = tid; idx < 4096; idx += 256)
            sW[idx] = W[(size_t)(kc * 32 + (idx >> 7)) * 128 + (idx & 127)];
        __syncthreads();
#pragma unroll 8
        for (int kk = 0; kk < 32; ++kk) {
            float w = sW[kk * 128 + col];
#pragma unroll
            for (int j = 0; j < 8; ++j)
                acc[j] = fmaf(sE[(sg * 8 + j) * 128 + kc * 32 + kk], w, acc[j]);
        }
    }
#pragma unroll
    for (int j = 0; j < 8; ++j) {
        int s = bbase + sg * 8 + j;
        if (s < Btot)
            g_vec[(size_t)which * Btot * 128 + (size_t)s * 128 + col] = acc[j];
    }
}

// ---------------- main kernel pieces ----------------
__device__ __forceinline__ void copy_unit(int u, uint32_t dstAddr, int tid) {
    const char* src = (const char*)g_wb + (size_t)u * 32768;
#pragma unroll
    for (int t = 0; t < 4; ++t) {
        int i = tid + t * NTHREADS;        // 0..2047 16B lines
        asm volatile("cp.async.cg.shared.global [%0], [%1], 16;"
                     :: "r"(dstAddr + i * 16), "l"(src + (size_t)i * 16));
    }
    asm volatile("cp.async.commit_group;" ::: "memory");
}

// single-term sweep over K=128: warp w owns rows [16w,16w+16) x full N=128.
__device__ __forceinline__ void sweep(
    float (&acc)[16][4],
    uint32_t aT, uint32_t bB,
    int w, int l)
{
    const int rA = 16 * w + (l & 15);
    const uint32_t aRowOff = (uint32_t)rA * 256;
    const int axor = rA & 7;
    const int khA = l >> 4;
    const uint32_t bLane = (uint32_t)(((l >> 4) & 1) * 2048 + (l & 7) * 256);
    const int bKh  = (l >> 3) & 1;
    const int bxor = l & 7;

#pragma unroll 1
    for (int ks = 0; ks < 8; ++ks) {
        uint32_t aoff = aRowOff + (uint32_t)(((2 * ks + khA) ^ axor) << 4);
        uint32_t a0, a1, a2, a3;
        LDSM4(a0, a1, a2, a3, aT + aoff);

        uint32_t bko = bLane + (uint32_t)(((2 * ks + bKh) ^ bxor) << 4);

        uint32_t bh[8][2];
#pragma unroll
        for (int p = 0; p < 4; ++p)
            LDSM4(bh[2 * p][0], bh[2 * p][1], bh[2 * p + 1][0], bh[2 * p + 1][1],
                  bB + (uint32_t)p * 4096 + bko);
#pragma unroll
        for (int t = 0; t < 8; ++t)
            MMA(acc[t], a0, a1, a2, a3, bh[t][0], bh[t][1]);
#pragma unroll
        for (int p = 0; p < 4; ++p)
            LDSM4(bh[2 * p][0], bh[2 * p][1], bh[2 * p + 1][0], bh[2 * p + 1][1],
                  bB + (uint32_t)(p + 4) * 4096 + bko);
#pragma unroll
        for (int t = 0; t < 8; ++t)
            MMA(acc[t + 8], a0, a1, a2, a3, bh[t][0], bh[t][1]);
    }
}

// gather table rows -> fp16 -> swizzled A tile (tile row = 50s+k)
__device__ __forceinline__ void gatherA(
    const float* __restrict__ tbl, const int* sIdx, char* smemc, int tid, int ns)
{
    for (int idx = tid; idx < ns * 800; idx += NTHREADS) {
        int rr = idx >> 4;                // tile row 0..50*ns-1
        int c = idx & 15;
        int u = sIdx[rr];
        const float4* src = (const float4*)(tbl + (size_t)u * 128 + c * 8);
        float4 v0 = src[0], v1 = src[1];
        uint4 hv = make_uint4(pkf2(v0.x, v0.y), pkf2(v0.z, v0.w),
                              pkf2(v1.x, v1.y), pkf2(v1.z, v1.w));
        *(uint4*)(smemc + SM_A + tile_off(rr, c)) = hv;
    }
}

// bias + relu -> fp16 back into A tile (opt: fp32 coup to gmem); resets acc.
// vec has per-sample stride vstride (0 = shared bias).
__device__ __forceinline__ void epilogueA(
    float (&acc)[16][4], char* smemc,
    const float* vec, int vstride,
    float* coupBase, int w, int l)
{
    int q  = 16 * w + (l >> 2);
    int p2 = (l & 3) * 2;
    int r0 = q, r1 = q + 8;
    int s0 = r0 / K_N; if (s0 > NS - 1) s0 = NS - 1;
    int s1 = r1 / K_N; if (s1 > NS - 1) s1 = NS - 1;
    const float* bv0 = vec + s0 * vstride;
    const float* bv1 = vec + s1 * vstride;
#pragma unroll
    for (int t = 0; t < 16; ++t) {
        int n = 8 * t + p2;
        float y00 = fmaxf(acc[t][0] + bv0[n],     0.f);
        float y01 = fmaxf(acc[t][1] + bv0[n + 1], 0.f);
        float y10 = fmaxf(acc[t][2] + bv1[n],     0.f);
        float y11 = fmaxf(acc[t][3] + bv1[n + 1], 0.f);
        acc[t][0] = 0.f; acc[t][1] = 0.f; acc[t][2] = 0.f; acc[t][3] = 0.f;
        *(uint32_t*)(smemc + SM_A + tile_off(r0, t) + p2 * 2) = pkf2(y00, y01);
        *(uint32_t*)(smemc + SM_A + tile_off(r1, t) + p2 * 2) = pkf2(y10, y11);
        if (coupBase) {
            *(float2*)(coupBase + (size_t)r0 * 128 + n) = make_float2(y00, y01);
            *(float2*)(coupBase + (size_t)r1 * 128 + n) = make_float2(y10, y11);
        }
    }
}

// last layer: bias+relu (shared ba2), dot with w3, quad reduce -> sScore[row]
__device__ __forceinline__ void epilogueScore(
    float (&acc)[16][4], const float* ba2, const float* w3, float b3,
    float* sScore, int w, int l)
{
    int q  = 16 * w + (l >> 2);
    int p2 = (l & 3) * 2;
    float p0 = 0.f, p1 = 0.f;
#pragma unroll
    for (int t = 0; t < 16; ++t) {
        int n = 8 * t + p2;
        p0 = fmaf(fmaxf(acc[t][0] + ba2[n],     0.f), w3[n],     p0);
        p0 = fmaf(fmaxf(acc[t][1] + ba2[n + 1], 0.f), w3[n + 1], p0);
        p1 = fmaf(fmaxf(acc[t][2] + ba2[n],     0.f), w3[n],     p1);
        p1 = fmaf(fmaxf(acc[t][3] + ba2[n + 1], 0.f), w3[n + 1], p1);
    }
    p0 += __shfl_xor_sync(0xffffffffu, p0, 1);
    p0 += __shfl_xor_sync(0xffffffffu, p0, 2);
    p1 += __shfl_xor_sync(0xffffffffu, p1, 1);
    p1 += __shfl_xor_sync(0xffffffffu, p1, 2);
    if ((l & 3) == 0) {
        sScore[q]     = p0 + b3;
        sScore[q + 8] = p1 + b3;
    }
}

#define WAITG(n) asm volatile("cp.async.wait_group %0;" :: "n"(n) : "memory")

__global__ __launch_bounds__(NTHREADS, 1)
void influence_main(
    const float* __restrict__ act_users_f,
    const float* __restrict__ emb_table, const float* __restrict__ prof_table,
    const float* __restrict__ b_fus, const float* __restrict__ b_c2,
    const float* __restrict__ b_a2,  const float* __restrict__ w_a3,
    const float* __restrict__ b_a3,
    int Btot,
    float* __restrict__ out_combined, float* __restrict__ out_att)
{
    extern __shared__ char smemc[];
    const int tid = threadIdx.x;
    const int w = tid >> 5, l = tid & 31;
    const int b0 = blockIdx.x * NS;
    const int ns = (Btot - b0 < NS) ? (Btot - b0) : NS;
    const int* act_users = (const int*)act_users_f;
    uint32_t sb = smem_u32(smemc);

    int* sIdx     = (int*)(smemc + SM_IDX);
    float* sBfus  = (float*)(smemc + SM_BFUS);
    float* sBc2   = (float*)(smemc + SM_BC2);
    float* sBa2   = (float*)(smemc + SM_BA2);
    float* sW3    = (float*)(smemc + SM_W3);
    float* sVC1   = (float*)(smemc + SM_VC1);
    float* sVA1   = (float*)(smemc + SM_VA1);
    float* sScore = (float*)(smemc + SM_SCORE);
    float* sAtt   = (float*)(smemc + SM_ATT);
    float* coup   = g_coup + (size_t)blockIdx.x * 32768;

    copy_unit(0, sb + SM_B0, tid);
    copy_unit(1, sb + SM_B1, tid);

    if (tid < NS * K_N) {
        int s = tid / K_N, k = tid - s * K_N;
        if (s < ns) sIdx[tid] = act_users[(size_t)(b0 + s) * K_N + k];
    }
    if (tid < 128) {
        sBfus[tid] = b_fus[tid];
        sBc2[tid]  = b_c2[tid];
        sBa2[tid]  = b_a2[tid];
        sW3[tid]   = w_a3[tid];
    }
    for (int idx = tid; idx < ns * 128; idx += NTHREADS) {
        int s = idx >> 7, c = idx & 127;
        sVC1[idx] = g_vec[(size_t)(b0 + s) * 128 + c];
        sVA1[idx] = g_vec[(size_t)Btot * 128 + (size_t)(b0 + s) * 128 + c];
    }
    __syncthreads();                       // sIdx visible
    gatherA(emb_table, sIdx, smemc, tid, ns);

    float acc[16][4];
#pragma unroll
    for (int t = 0; t < 16; ++t) {
        acc[t][0] = 0.f; acc[t][1] = 0.f; acc[t][2] = 0.f; acc[t][3] = 0.f;
    }

    WAITG(1); __syncthreads();             // A(emb) + unit0 ready
    sweep(acc, sb + SM_A, sb + SM_B0, w, l);
    __syncthreads();                       // B0 free, A free
    copy_unit(2, sb + SM_B0, tid);
    gatherA(prof_table, sIdx, smemc, tid, ns);
    WAITG(1); __syncthreads();             // A(prof) + unit1 ready
    sweep(acc, sb + SM_A, sb + SM_B1, w, l);
    __syncthreads();                       // B1 free, A free
    copy_unit(3, sb + SM_B1, tid);
    epilogueA(acc, smemc, sBfus, 0, nullptr, w, l);          // L1 -> fused
    WAITG(1); __syncthreads();
    sweep(acc, sb + SM_A, sb + SM_B0, w, l);                 // L2
    __syncthreads();
    copy_unit(4, sb + SM_B0, tid);
    epilogueA(acc, smemc, sVC1, 128, nullptr, w, l);         // L2 -> c1
    WAITG(1); __syncthreads();
    sweep(acc, sb + SM_A, sb + SM_B1, w, l);                 // L3
    __syncthreads();
    copy_unit(5, sb + SM_B1, tid);
    epilogueA(acc, smemc, sBc2, 0, coup, w, l);              // L3 -> coup (+gmem)
    WAITG(1); __syncthreads();
    sweep(acc, sb + SM_A, sb + SM_B0, w, l);                 // L4
    __syncthreads();
    epilogueA(acc, smemc, sVA1, 128, nullptr, w, l);         // L4 -> h
    WAITG(0); __syncthreads();
    sweep(acc, sb + SM_A, sb + SM_B1, w, l);                 // L5
    epilogueScore(acc, sBa2, sW3, b_a3[0], sScore, w, l);
    __syncthreads();

    // softmax per sample: warp s handles sample s (tile-row base 50s)
    if (w < ns) {
        int base = K_N * w;
        float v1 = (l < K_N)      ? sScore[base + l]      : -1e30f;
        float v2 = (l + 32 < K_N) ? sScore[base + l + 32] : -1e30f;
        float m = fmaxf(v1, v2);
#pragma unroll
        for (int o = 16; o; o >>= 1)
            m = fmaxf(m, __shfl_xor_sync(0xffffffffu, m, o));
        float e1 = (l < K_N)      ? expf(v1 - m) : 0.f;
        float e2 = (l + 32 < K_N) ? expf(v2 - m) : 0.f;
        float sum = e1 + e2;
#pragma unroll
        for (int o = 16; o; o >>= 1)
            sum += __shfl_xor_sync(0xffffffffu, sum, o);
        float inv = 1.f / sum;
        if (l < K_N)      sAtt[w * 64 + l]      = e1 * inv;
        if (l + 32 < K_N) sAtt[w * 64 + l + 32] = e2 * inv;
    }
    __syncthreads();

    // combined[s][col] = sum_k att[s][k] * coup[50s+k][col]
    for (int idx = tid; idx < ns * 128; idx += NTHREADS) {
        int s = idx >> 7, col = idx & 127;
        float a = 0.f;
#pragma unroll 2
        for (int k = 0; k < K_N; ++k)
            a = fmaf(sAtt[s * 64 + k], coup[(size_t)(K_N * s + k) * 128 + col], a);
        out_combined[(size_t)(b0 + s) * 128 + col] = a;
    }
    if (tid < ns * K_N) {
        int s = tid / K_N, k = tid - s * K_N;
        out_att[(size_t)(b0 + s) * K_N + k] = sAtt[s * 64 + k];
    }
}

// ---------------- host launcher ----------------
extern "C" void kernel_launch(void* const* d_in, const int* in_sizes, int n_in,
                              void* d_out, int out_size) {
    const float* u_embs = (const float*)d_in[1];
    const float* i_embs = (const float*)d_in[3];
    const float* act    = (const float*)d_in[4];   // int32 data
    const float* table  = (const float*)d_in[5];
    const float* prof   = (const float*)d_in[6];
    const float* w_fus  = (const float*)d_in[7];
    const float* b_fus  = (const float*)d_in[8];
    const float* w_c1   = (const float*)d_in[9];
    const float* b_c1   = (const float*)d_in[10];
    const float* w_c2   = (const float*)d_in[11];
    const float* b_c2   = (const float*)d_in[12];
    const float* w_a1   = (const float*)d_in[13];
    const float* b_a1   = (const float*)d_in[14];
    const float* w_a2   = (const float*)d_in[15];
    const float* b_a2   = (const float*)d_in[16];
    const float* w_a3   = (const float*)d_in[17];
    const float* b_a3   = (const float*)d_in[18];

    int B = in_sizes[0];   // 4096

    float* out_combined = (float*)d_out;
    float* out_att      = out_combined + (size_t)B * 128;

    prep_weights<<<48, 256>>>(w_fus, w_c1, w_c2, w_a1, w_a2);
    prep_vecs2<<<dim3((B + 15) / 16, 2), 256>>>(i_embs, u_embs,
                                                w_c1, b_c1, w_a1, b_a1, B);

    int grid = (B + NS - 1) / NS;
    cudaFuncSetAttribute(influence_main,
                         cudaFuncAttributeMaxDynamicSharedMemorySize, SM_TOTAL);
    influence_main<<<grid, NTHREADS, SM_TOTAL>>>(
        act, table, prof,
        b_fus, b_c2, b_a2, w_a3, b_a3, B,
        out_combined, out_att);
}

// round 13
// speedup vs baseline: 4.4651x; 1.1988x over previous
#include <cuda_runtime.h>
#include <cuda_fp16.h>
#include <cstdint>

// InfluenceProp R13: single-term fp16 HMMA on a fully-packed row space.
// G = B*50 global rows; each CTA owns 128 rows (no pad rows at all), 256 thr,
// 2 CTAs/SM. Samples may straddle CTAs: per-row folded-bias select from <=4
// staged vectors; L5 scores and L3 coup spill to gmem; a small finish kernel
// does per-sample softmax + aggregation. Prepasses fused into one kernel.

#define K_N 50

// ---------------- gmem scratch ----------------
__device__ __align__(1024) __half g_wb[6 * 16384];   // 6 units x 128x128 fp16
__device__ float g_vec[2ull * 4096 * 128];           // folded biases [which][b][128]
__device__ float g_coup[204800ull * 128];            // coup fp32 per global row
__device__ float g_score[204928];                    // raw scores per global row

// ---------------- smem byte offsets ----------------
#define SM_A     0          // 128x128 fp16 swizzled (32KB)
#define SM_B0    32768      // 128x128 fp16 (32KB)
#define SM_B1    65536
#define SM_IDX   98304      // 128 ints
#define SM_BFUS  98816
#define SM_BC2   99328
#define SM_BA2   99840
#define SM_W3    100352
#define SM_VC1   100864     // [4][128] f
#define SM_VA1   102912     // [4][128] f
#define SM_TOTAL 104960

// tile layout: row r, 256 B/row; 16B chunk c stored at (c ^ (r&7))
__device__ __host__ __forceinline__ int tile_off(int r, int c) {
    return r * 256 + ((c ^ (r & 7)) << 4);
}

__device__ __forceinline__ uint32_t smem_u32(const void* p) {
    uint32_t a;
    asm("{ .reg .u64 t; cvta.to.shared.u64 t, %1; cvt.u32.u64 %0, t; }" : "=r"(a) : "l"(p));
    return a;
}

#define LDSM4(r0, r1, r2, r3, addr) \
    asm volatile("ldmatrix.sync.aligned.m8n8.x4.shared.b16 {%0,%1,%2,%3}, [%4];" \
                 : "=r"(r0), "=r"(r1), "=r"(r2), "=r"(r3) : "r"(addr))
#define MMA(ac, a0, a1, a2, a3, b0, b1) \
    asm volatile("mma.sync.aligned.m16n8k16.row.col.f32.f16.f16.f32 " \
                 "{%0,%1,%2,%3},{%4,%5,%6,%7},{%8,%9},{%0,%1,%2,%3};" \
                 : "+f"((ac)[0]), "+f"((ac)[1]), "+f"((ac)[2]), "+f"((ac)[3]) \
                 : "r"(a0), "r"(a1), "r"(a2), "r"(a3), "r"(b0), "r"(b1))

__device__ __forceinline__ uint32_t pkf2(float a, float b) {
    __half2 t = __floats2half2_rn(a, b);
    uint32_t u; __builtin_memcpy(&u, &t, 4);
    return u;
}

// ---------------- fused prepass: weights + folded bias vectors ----------------
__global__ void prep_all(
    const float* __restrict__ w_fus, const float* __restrict__ w_c1,
    const float* __restrict__ w_c2,  const float* __restrict__ w_a1,
    const float* __restrict__ w_a2,
    const float* __restrict__ i_embs, const float* __restrict__ u_embs,
    const float* __restrict__ b_c1,   const float* __restrict__ b_a1,
    int Btot)
{
    int bid = blockIdx.x;
    int tid = threadIdx.x;
    if (bid < 48) {
        // weight fp16 + transpose + swizzle
        int u = bid >> 3;
        int part = bid & 7;
        const float* base; int koff = 0;
        if      (u == 0) { base = w_fus; }
        else if (u == 1) { base = w_fus; koff = 128; }
        else if (u == 2) { base = w_c1; }
        else if (u == 3) { base = w_c2; }
        else if (u == 4) { base = w_a1; }
        else             { base = w_a2; }
        int e0 = part * 2048;
        for (int i = tid; i < 2048; i += blockDim.x) {
            int e = e0 + i;
            int n = e >> 7, k = e & 127;
            float v = base[(size_t)(k + koff) * 128 + n];
            int elem = (n * 256 + (((k >> 3) ^ (n & 7)) << 4) + (k & 7) * 2) >> 1;
            g_wb[(size_t)u * 16384 + elem] = __float2half_rn(v);
        }
        return;
    }
    // folded bias vectors: 16 samples per block
    __shared__ float sE[16 * 128];
    __shared__ float sW[32 * 128];
    int v = bid - 48;
    int which = v & 1;
    int bbase = (v >> 1) * 16;
    const float* emb = which ? u_embs : i_embs;
    const float* W   = (which ? w_a1 : w_c1) + (size_t)128 * 128;
    const float* bb  = which ? b_a1 : b_c1;

    for (int idx = tid; idx < 2048; idx += 256) {
        int s = idx >> 7, c = idx & 127;
        sE[idx] = (bbase + s < Btot) ? emb[(size_t)(bbase + s) * 128 + c] : 0.f;
    }
    int col = tid & 127;
    int sg  = tid >> 7;
    float acc[8];
#pragma unroll
    for (int j = 0; j < 8; ++j) acc[j] = bb[col];

    for (int kc = 0; kc < 4; ++kc) {
        __syncthreads();
        for (int idx = tid; idx < 4096; idx += 256)
            sW[idx] = W[(size_t)(kc * 32 + (idx >> 7)) * 128 + (idx & 127)];
        __syncthreads();
#pragma unroll 8
        for (int kk = 0; kk < 32; ++kk) {
            float w = sW[kk * 128 + col];
#pragma unroll
            for (int j = 0; j < 8; ++j)
                acc[j] = fmaf(sE[(sg * 8 + j) * 128 + kc * 32 + kk], w, acc[j]);
        }
    }
#pragma unroll
    for (int j = 0; j < 8; ++j) {
        int s = bbase + sg * 8 + j;
        if (s < Btot)
            g_vec[(size_t)which * Btot * 128 + (size_t)s * 128 + col] = acc[j];
    }
}

// ---------------- main kernel pieces ----------------
__device__ __forceinline__ void copy_unit(int u, uint32_t dstAddr, int tid) {
    const char* src = (const char*)g_wb + (size_t)u * 32768;
#pragma unroll
    for (int t = 0; t < 8; ++t) {
        int i = tid + t * 256;             // 0..2047 16B lines
        asm volatile("cp.async.cg.shared.global [%0], [%1], 16;"
                     :: "r"(dstAddr + i * 16), "l"(src + (size_t)i * 16));
    }
    asm volatile("cp.async.commit_group;" ::: "memory");
}

// single-term sweep over K=128: warp w owns rows [16w,16w+16) x full N=128.
__device__ __forceinline__ void sweep(
    float (&acc)[16][4],
    uint32_t aT, uint32_t bB,
    int w, int l)
{
    const int rA = 16 * w + (l & 15);
    const uint32_t aRowOff = (uint32_t)rA * 256;
    const int axor = rA & 7;
    const int khA = l >> 4;
    const uint32_t bLane = (uint32_t)(((l >> 4) & 1) * 2048 + (l & 7) * 256);
    const int bKh  = (l >> 3) & 1;
    const int bxor = l & 7;

#pragma unroll 1
    for (int ks = 0; ks < 8; ++ks) {
        uint32_t aoff = aRowOff + (uint32_t)(((2 * ks + khA) ^ axor) << 4);
        uint32_t a0, a1, a2, a3;
        LDSM4(a0, a1, a2, a3, aT + aoff);

        uint32_t bko = bLane + (uint32_t)(((2 * ks + bKh) ^ bxor) << 4);

        uint32_t bh[8][2];
#pragma unroll
        for (int p = 0; p < 4; ++p)
            LDSM4(bh[2 * p][0], bh[2 * p][1], bh[2 * p + 1][0], bh[2 * p + 1][1],
                  bB + (uint32_t)p * 4096 + bko);
#pragma unroll
        for (int t = 0; t < 8; ++t)
            MMA(acc[t], a0, a1, a2, a3, bh[t][0], bh[t][1]);
#pragma unroll
        for (int p = 0; p < 4; ++p)
            LDSM4(bh[2 * p][0], bh[2 * p][1], bh[2 * p + 1][0], bh[2 * p + 1][1],
                  bB + (uint32_t)(p + 4) * 4096 + bko);
#pragma unroll
        for (int t = 0; t < 8; ++t)
            MMA(acc[t + 8], a0, a1, a2, a3, bh[t][0], bh[t][1]);
    }
}

// gather table rows -> fp16 -> swizzled A tile (all 128 local rows valid)
__device__ __forceinline__ void gatherA(
    const float* __restrict__ tbl, const int* sIdx, char* smemc, int tid)
{
    for (int idx = tid; idx < 2048; idx += 256) {
        int r = idx >> 4;
        int c = idx & 15;
        int u = sIdx[r];
        const float4* src = (const float4*)(tbl + (size_t)u * 128 + c * 8);
        float4 v0 = src[0], v1 = src[1];
        uint4 hv = make_uint4(pkf2(v0.x, v0.y), pkf2(v0.z, v0.w),
                              pkf2(v1.x, v1.y), pkf2(v1.z, v1.w));
        *(uint4*)(smemc + SM_A + tile_off(r, c)) = hv;
    }
}

// bias + relu -> fp16 back into A tile (opt: fp32 coup to gmem); resets acc.
// vec indexed by (global_sample - s_first) * vstride (vstride 0 = shared).
__device__ __forceinline__ void epilogueA(
    float (&acc)[16][4], char* smemc,
    const float* vec, int vstride,
    int gBase, int s_first,
    float* coupG, int w, int l)
{
    int q  = 16 * w + (l >> 2);
    int p2 = (l & 3) * 2;
    int r0 = q, r1 = q + 8;
    int s0 = (gBase + r0) / K_N - s_first;
    int s1 = (gBase + r1) / K_N - s_first;
    const float* bv0 = vec + s0 * vstride;
    const float* bv1 = vec + s1 * vstride;
#pragma unroll
    for (int t = 0; t < 16; ++t) {
        int n = 8 * t + p2;
        float y00 = fmaxf(acc[t][0] + bv0[n],     0.f);
        float y01 = fmaxf(acc[t][1] + bv0[n + 1], 0.f);
        float y10 = fmaxf(acc[t][2] + bv1[n],     0.f);
        float y11 = fmaxf(acc[t][3] + bv1[n + 1], 0.f);
        acc[t][0] = 0.f; acc[t][1] = 0.f; acc[t][2] = 0.f; acc[t][3] = 0.f;
        *(uint32_t*)(smemc + SM_A + tile_off(r0, t) + p2 * 2) = pkf2(y00, y01);
        *(uint32_t*)(smemc + SM_A + tile_off(r1, t) + p2 * 2) = pkf2(y10, y11);
        if (coupG) {
            *(float2*)(coupG + (size_t)(gBase + r0) * 128 + n) = make_float2(y00, y01);
            *(float2*)(coupG + (size_t)(gBase + r1) * 128 + n) = make_float2(y10, y11);
        }
    }
}

// last layer: bias+relu (shared ba2), dot w3, quad reduce -> g_score[global row]
__device__ __forceinline__ void epilogueScore(
    float (&acc)[16][4], const float* ba2, const float* w3, float b3,
    int gBase, int w, int l)
{
    int q  = 16 * w + (l >> 2);
    int p2 = (l & 3) * 2;
    float p0 = 0.f, p1 = 0.f;
#pragma unroll
    for (int t = 0; t < 16; ++t) {
        int n = 8 * t + p2;
        p0 = fmaf(fmaxf(acc[t][0] + ba2[n],     0.f), w3[n],     p0);
        p0 = fmaf(fmaxf(acc[t][1] + ba2[n + 1], 0.f), w3[n + 1], p0);
        p1 = fmaf(fmaxf(acc[t][2] + ba2[n],     0.f), w3[n],     p1);
        p1 = fmaf(fmaxf(acc[t][3] + ba2[n + 1], 0.f), w3[n + 1], p1);
    }
    p0 += __shfl_xor_sync(0xffffffffu, p0, 1);
    p0 += __shfl_xor_sync(0xffffffffu, p0, 2);
    p1 += __shfl_xor_sync(0xffffffffu, p1, 1);
    p1 += __shfl_xor_sync(0xffffffffu, p1, 2);
    if ((l & 3) == 0) {
        g_score[gBase + q]     = p0 + b3;
        g_score[gBase + q + 8] = p1 + b3;
    }
}

#define WAITG(n) asm volatile("cp.async.wait_group %0;" :: "n"(n) : "memory")

__global__ __launch_bounds__(256, 2)
void influence_main(
    const float* __restrict__ act_users_f,
    const float* __restrict__ emb_table, const float* __restrict__ prof_table,
    const float* __restrict__ b_fus, const float* __restrict__ b_c2,
    const float* __restrict__ b_a2,  const float* __restrict__ w_a3,
    const float* __restrict__ b_a3,
    int Btot)
{
    extern __shared__ char smemc[];
    const int tid = threadIdx.x;
    const int w = tid >> 5, l = tid & 31;
    const int gBase = blockIdx.x * 128;
    const int G = Btot * K_N;
    const int s_first = gBase / K_N;
    const int* act_users = (const int*)act_users_f;   // flat [B*50]
    uint32_t sb = smem_u32(smemc);

    int* sIdx     = (int*)(smemc + SM_IDX);
    float* sBfus  = (float*)(smemc + SM_BFUS);
    float* sBc2   = (float*)(smemc + SM_BC2);
    float* sBa2   = (float*)(smemc + SM_BA2);
    float* sW3    = (float*)(smemc + SM_W3);
    float* sVC1   = (float*)(smemc + SM_VC1);
    float* sVA1   = (float*)(smemc + SM_VA1);

    copy_unit(0, sb + SM_B0, tid);
    copy_unit(1, sb + SM_B1, tid);

    if (tid < 128) {
        int g = gBase + tid;
        sIdx[tid] = (g < G) ? act_users[g] : 0;
    } else {
        int c = tid - 128;
        sBfus[c] = b_fus[c];
        sBc2[c]  = b_c2[c];
        sBa2[c]  = b_a2[c];
        sW3[c]   = w_a3[c];
    }
    // stage up to 4 per-sample folded bias vectors
    for (int idx = tid; idx < 4 * 128; idx += 256) {
        int j = idx >> 7, c = idx & 127;
        int s = s_first + j; if (s > Btot - 1) s = Btot - 1;
        sVC1[idx] = g_vec[(size_t)s * 128 + c];
        sVA1[idx] = g_vec[(size_t)Btot * 128 + (size_t)s * 128 + c];
    }
    __syncthreads();                       // sIdx visible
    gatherA(emb_table, sIdx, smemc, tid);

    float acc[16][4];
#pragma unroll
    for (int t = 0; t < 16; ++t) {
        acc[t][0] = 0.f; acc[t][1] = 0.f; acc[t][2] = 0.f; acc[t][3] = 0.f;
    }

    WAITG(1); __syncthreads();             // A(emb) + unit0 ready
    sweep(acc, sb + SM_A, sb + SM_B0, w, l);
    __syncthreads();                       // B0 free, A free
    copy_unit(2, sb + SM_B0, tid);
    gatherA(prof_table, sIdx, smemc, tid);
    WAITG(1); __syncthreads();             // A(prof) + unit1 ready
    sweep(acc, sb + SM_A, sb + SM_B1, w, l);
    __syncthreads();                       // B1 free, A free
    copy_unit(3, sb + SM_B1, tid);
    epilogueA(acc, smemc, sBfus, 0, gBase, s_first, nullptr, w, l);   // L1
    WAITG(1); __syncthreads();
    sweep(acc, sb + SM_A, sb + SM_B0, w, l);                          // L2
    __syncthreads();
    copy_unit(4, sb + SM_B0, tid);
    epilogueA(acc, smemc, sVC1, 128, gBase, s_first, nullptr, w, l);  // L2 -> c1
    WAITG(1); __syncthreads();
    sweep(acc, sb + SM_A, sb + SM_B1, w, l);                          // L3
    __syncthreads();
    copy_unit(5, sb + SM_B1, tid);
    epilogueA(acc, smemc, sBc2, 0, gBase, s_first, g_coup, w, l);     // L3 -> coup
    WAITG(1); __syncthreads();
    sweep(acc, sb + SM_A, sb + SM_B0, w, l);                          // L4
    __syncthreads();
    epilogueA(acc, smemc, sVA1, 128, gBase, s_first, nullptr, w, l);  // L4 -> h
    WAITG(0); __syncthreads();
    sweep(acc, sb + SM_A, sb + SM_B1, w, l);                          // L5
    epilogueScore(acc, sBa2, sW3, b_a3[0], gBase, w, l);
}

// ---------------- finish: per-sample softmax + aggregation ----------------
__global__ __launch_bounds__(128)
void influence_finish(
    float* __restrict__ out_combined, float* __restrict__ out_att)
{
    __shared__ float sAtt[64];
    int s = blockIdx.x;
    int tid = threadIdx.x;
    int l = tid & 31;

    if (tid < 32) {
        float v1 = (l < K_N)      ? g_score[s * K_N + l]      : -1e30f;
        float v2 = (l + 32 < K_N) ? g_score[s * K_N + l + 32] : -1e30f;
        float m = fmaxf(v1, v2);
#pragma unroll
        for (int o = 16; o; o >>= 1)
            m = fmaxf(m, __shfl_xor_sync(0xffffffffu, m, o));
        float e1 = (l < K_N)      ? expf(v1 - m) : 0.f;
        float e2 = (l + 32 < K_N) ? expf(v2 - m) : 0.f;
        float sum = e1 + e2;
#pragma unroll
        for (int o = 16; o; o >>= 1)
            sum += __shfl_xor_sync(0xffffffffu, sum, o);
        float inv = 1.f / sum;
        if (l < K_N)      sAtt[l]      = e1 * inv;
        if (l + 32 < K_N) sAtt[l + 32] = e2 * inv;
    }
    __syncthreads();

    float a = 0.f;
    const float* cp = g_coup + (size_t)s * K_N * 128 + tid;
#pragma unroll 2
    for (int k = 0; k < K_N; ++k)
        a = fmaf(sAtt[k], cp[k * 128], a);
    out_combined[(size_t)s * 128 + tid] = a;
    if (tid < K_N)
        out_att[(size_t)s * K_N + tid] = sAtt[tid];
}

// ---------------- host launcher ----------------
extern "C" void kernel_launch(void* const* d_in, const int* in_sizes, int n_in,
                              void* d_out, int out_size) {
    const float* u_embs = (const float*)d_in[1];
    const float* i_embs = (const float*)d_in[3];
    const float* act    = (const float*)d_in[4];   // int32 data
    const float* table  = (const float*)d_in[5];
    const float* prof   = (const float*)d_in[6];
    const float* w_fus  = (const float*)d_in[7];
    const float* b_fus  = (const float*)d_in[8];
    const float* w_c1   = (const float*)d_in[9];
    const float* b_c1   = (const float*)d_in[10];
    const float* w_c2   = (const float*)d_in[11];
    const float* b_c2   = (const float*)d_in[12];
    const float* w_a1   = (const float*)d_in[13];
    const float* b_a1   = (const float*)d_in[14];
    const float* w_a2   = (const float*)d_in[15];
    const float* b_a2   = (const float*)d_in[16];
    const float* w_a3   = (const float*)d_in[17];
    const float* b_a3   = (const float*)d_in[18];

    int B = in_sizes[0];   // 4096

    float* out_combined = (float*)d_out;
    float* out_att      = out_combined + (size_t)B * 128;

    int vblocks = ((B + 15) / 16) * 2;
    prep_all<<<48 + vblocks, 256>>>(w_fus, w_c1, w_c2, w_a1, w_a2,
                                    i_embs, u_embs, b_c1, b_a1, B);

    int G = B * K_N;
    int grid = (G + 127) / 128;            // 1600 for B=4096 (exact)
    cudaFuncSetAttribute(influence_main,
                         cudaFuncAttributeMaxDynamicSharedMemorySize, SM_TOTAL);
    influence_main<<<grid, 256, SM_TOTAL>>>(
        act, table, prof,
        b_fus, b_c2, b_a2, w_a3, b_a3, B);

    influence_finish<<<B, 128>>>(out_combined, out_att);
}